// round 1
// baseline (speedup 1.0000x reference)
#include <cuda_runtime.h>

// ---------------- problem constants ----------------
#define T_STEPS 300
#define BATCH   256
#define HID     128
#define D_IN    700
#define LAYERS  4
#define OUTD    20
#define M_TOTAL (T_STEPS * BATCH)   // 76800

// output buffer layout (tuple concatenated, fp32):
//   out      [256,20]        @ 0
//   hid4_mem [256,301,128]   @ 5120
//   hid4_spk [256,301,128]   @ 5120 + 9861128
//   A_norm   scalar          @ 5120 + 2*9861128
#define OUT_OFF  0
#define MEM_OFF  (BATCH * OUTD)                            // 5120
#define SPK_OFF  (MEM_OFF + BATCH * (T_STEPS + 1) * HID)   // 9866248
#define NORM_OFF (SPK_OFF + BATCH * (T_STEPS + 1) * HID)   // 19727376

// ---------------- scratch (device globals; no allocations) ----------------
__device__ float g_inp[M_TOTAL * HID];                     // [T][B][H]  39.3 MB
__device__ float g_xs[(size_t)LAYERS * M_TOTAL * HID];     // [L][T*B][H] 157 MB
__device__ float g_rates[LAYERS * BATCH * HID];

// ---------------- packed fp32x2 helpers ----------------
__device__ __forceinline__ void fma2(unsigned long long& c, unsigned long long a,
                                     unsigned long long b) {
    asm("fma.rn.f32x2 %0, %1, %2, %0;" : "+l"(c) : "l"(a), "l"(b));
}
__device__ __forceinline__ unsigned long long dup2(float x) {
    unsigned long long r;
    asm("mov.b64 %0, {%1, %2};" : "=l"(r) : "f"(x), "f"(x));
    return r;
}
__device__ __forceinline__ float2 unpack2(unsigned long long v) {
    float2 f;
    asm("mov.b64 {%0, %1}, %2;" : "=f"(f.x), "=f"(f.y) : "l"(v));
    return f;
}

// ============================================================
// GEMM1: inp[t*256+b][h] = sum_d x[b*300+t][d] * w_in[d][h] + b_in[h]
// BM=128, BN=128, BK=8, 256 threads, 8x8 thread tile (rows paired for f32x2)
// ============================================================
__global__ __launch_bounds__(256) void gemm_in(const float* __restrict__ x,
                                               const float* __restrict__ w,
                                               const float* __restrict__ bias) {
    __shared__ float As[8][128];   // [k][m] transposed
    __shared__ float Bs[8][128];   // [k][n]
    const int tid = threadIdx.x;
    const int m0 = blockIdx.x * 128;
    const int tx = tid & 15, ty = tid >> 4;

    const int ar = tid >> 1;          // row in A tile
    const int ak = (tid & 1) * 4;     // k sub-offset
    const int bk = tid >> 5;          // k row for B tile
    const int bc = (tid & 31) * 4;    // col for B tile

    unsigned long long acc[4][8];
#pragma unroll
    for (int p = 0; p < 4; p++)
#pragma unroll
        for (int j = 0; j < 8; j++) acc[p][j] = 0ull;

    for (int k0 = 0; k0 < D_IN; k0 += 8) {
        float4 va = make_float4(0.f, 0.f, 0.f, 0.f);
        int ka = k0 + ak;
        if (ka < D_IN) va = *(const float4*)(x + (size_t)(m0 + ar) * D_IN + ka);
        As[ak + 0][ar] = va.x; As[ak + 1][ar] = va.y;
        As[ak + 2][ar] = va.z; As[ak + 3][ar] = va.w;

        float4 vb = make_float4(0.f, 0.f, 0.f, 0.f);
        int kb = k0 + bk;
        if (kb < D_IN) vb = *(const float4*)(w + (size_t)kb * HID + bc);
        *(float4*)&Bs[bk][bc] = vb;
        __syncthreads();

#pragma unroll
        for (int kk = 0; kk < 8; kk++) {
            unsigned long long a2[4];
            const unsigned long long* Ap =
                (const unsigned long long*)&As[kk][ty * 8];
            a2[0] = Ap[0]; a2[1] = Ap[1]; a2[2] = Ap[2]; a2[3] = Ap[3];
            const float4* Bp = (const float4*)&Bs[kk][tx * 8];
            float4 b0 = Bp[0], b1 = Bp[1];
            unsigned long long b2[8];
            b2[0] = dup2(b0.x); b2[1] = dup2(b0.y); b2[2] = dup2(b0.z); b2[3] = dup2(b0.w);
            b2[4] = dup2(b1.x); b2[5] = dup2(b1.y); b2[6] = dup2(b1.z); b2[7] = dup2(b1.w);
#pragma unroll
            for (int p = 0; p < 4; p++)
#pragma unroll
                for (int j = 0; j < 8; j++) fma2(acc[p][j], a2[p], b2[j]);
        }
        __syncthreads();
    }

    float bb[8];
#pragma unroll
    for (int j = 0; j < 8; j++) bb[j] = bias[tx * 8 + j];

#pragma unroll
    for (int p = 0; p < 4; p++) {
        float lo[8], hi[8];
#pragma unroll
        for (int j = 0; j < 8; j++) {
            float2 v = unpack2(acc[p][j]);
            lo[j] = v.x + bb[j];
            hi[j] = v.y + bb[j];
        }
        int m_lo = m0 + ty * 8 + 2 * p;
        {
            int b_ = m_lo / T_STEPS, t_ = m_lo % T_STEPS;
            float* o = g_inp + (size_t)(t_ * BATCH + b_) * HID + tx * 8;
            *(float4*)o = make_float4(lo[0], lo[1], lo[2], lo[3]);
            *(float4*)(o + 4) = make_float4(lo[4], lo[5], lo[6], lo[7]);
        }
        {
            int m_hi = m_lo + 1;
            int b_ = m_hi / T_STEPS, t_ = m_hi % T_STEPS;
            float* o = g_inp + (size_t)(t_ * BATCH + b_) * HID + tx * 8;
            *(float4*)o = make_float4(hi[0], hi[1], hi[2], hi[3]);
            *(float4*)(o + 4) = make_float4(hi[4], hi[5], hi[6], hi[7]);
        }
    }
}

// ============================================================
// GEMM2: xs[l][m][n] = sum_k inp[m][k] * A_w[l][k][n] + A_b[l][n]
// (m = t*256+b ordering; K = 128)
// ============================================================
__global__ __launch_bounds__(256) void gemm_res(const float* __restrict__ Aw,
                                                const float* __restrict__ Ab) {
    __shared__ float As[8][128];
    __shared__ float Bs[8][128];
    const int tid = threadIdx.x;
    const int m0 = blockIdx.x * 128;
    const int l = blockIdx.y;
    const int tx = tid & 15, ty = tid >> 4;

    const float* w = Aw + (size_t)l * HID * HID;
    float* out = g_xs + (size_t)l * M_TOTAL * HID;

    const int ar = tid >> 1;
    const int ak = (tid & 1) * 4;
    const int bk = tid >> 5;
    const int bc = (tid & 31) * 4;

    unsigned long long acc[4][8];
#pragma unroll
    for (int p = 0; p < 4; p++)
#pragma unroll
        for (int j = 0; j < 8; j++) acc[p][j] = 0ull;

    for (int k0 = 0; k0 < HID; k0 += 8) {
        float4 va = *(const float4*)(g_inp + (size_t)(m0 + ar) * HID + k0 + ak);
        As[ak + 0][ar] = va.x; As[ak + 1][ar] = va.y;
        As[ak + 2][ar] = va.z; As[ak + 3][ar] = va.w;
        float4 vb = *(const float4*)(w + (size_t)(k0 + bk) * HID + bc);
        *(float4*)&Bs[bk][bc] = vb;
        __syncthreads();

#pragma unroll
        for (int kk = 0; kk < 8; kk++) {
            unsigned long long a2[4];
            const unsigned long long* Ap =
                (const unsigned long long*)&As[kk][ty * 8];
            a2[0] = Ap[0]; a2[1] = Ap[1]; a2[2] = Ap[2]; a2[3] = Ap[3];
            const float4* Bp = (const float4*)&Bs[kk][tx * 8];
            float4 b0 = Bp[0], b1 = Bp[1];
            unsigned long long b2[8];
            b2[0] = dup2(b0.x); b2[1] = dup2(b0.y); b2[2] = dup2(b0.z); b2[3] = dup2(b0.w);
            b2[4] = dup2(b1.x); b2[5] = dup2(b1.y); b2[6] = dup2(b1.z); b2[7] = dup2(b1.w);
#pragma unroll
            for (int p = 0; p < 4; p++)
#pragma unroll
                for (int j = 0; j < 8; j++) fma2(acc[p][j], a2[p], b2[j]);
        }
        __syncthreads();
    }

    float bb[8];
#pragma unroll
    for (int j = 0; j < 8; j++) bb[j] = Ab[l * HID + tx * 8 + j];

#pragma unroll
    for (int p = 0; p < 4; p++) {
        float lo[8], hi[8];
#pragma unroll
        for (int j = 0; j < 8; j++) {
            float2 v = unpack2(acc[p][j]);
            lo[j] = v.x + bb[j];
            hi[j] = v.y + bb[j];
        }
        int m_lo = m0 + ty * 8 + 2 * p;
        float* o0 = out + (size_t)m_lo * HID + tx * 8;
        *(float4*)o0 = make_float4(lo[0], lo[1], lo[2], lo[3]);
        *(float4*)(o0 + 4) = make_float4(lo[4], lo[5], lo[6], lo[7]);
        float* o1 = out + (size_t)(m_lo + 1) * HID + tx * 8;
        *(float4*)o1 = make_float4(hi[0], hi[1], hi[2], hi[3]);
        *(float4*)(o1 + 4) = make_float4(hi[4], hi[5], hi[6], hi[7]);
    }
}

// ============================================================
// Sequential LIF scan over T. block = (b, l), thread = neuron h.
// t-unroll=10 gives MLP=10 on the strided xs loads.
// ============================================================
__global__ void scan_kernel(const float* __restrict__ mem0,
                            const float* __restrict__ thr,
                            const float* __restrict__ decay,
                            const float* __restrict__ rstv,
                            float* __restrict__ dout) {
    const int b = blockIdx.x;
    const int l = blockIdx.y;
    const int h = threadIdx.x;

    const float* xp = g_xs + (size_t)l * M_TOTAL * HID + (size_t)b * HID + h;
    float mem = mem0[(l * BATCH + b) * HID + h];
    float spk = 0.f, rate = 0.f;
    const float th = thr[h], dc = decay[h], rs = rstv[h];
    const bool last = (l == 3);

    float* mo = dout + MEM_OFF + (size_t)b * (T_STEPS + 1) * HID + h;
    float* so = dout + SPK_OFF + (size_t)b * (T_STEPS + 1) * HID + h;
    if (last) { mo[0] = mem; so[0] = 0.f; }

    const int ST = BATCH * HID;  // per-t stride: 32768 floats
    for (int t = 0; t < T_STEPS; t += 10) {
        float v[10];
#pragma unroll
        for (int j = 0; j < 10; j++) v[j] = xp[(size_t)(t + j) * ST];
#pragma unroll
        for (int j = 0; j < 10; j++) {
            mem = rs * spk + mem * dc * (1.f - spk) + v[j];
            spk = (mem - th > 0.f) ? 1.f : 0.f;
            rate += spk;
            if (last) {
                mo[(size_t)(t + j + 1) * HID] = mem;
                so[(size_t)(t + j + 1) * HID] = spk;
            }
        }
    }
    g_rates[(l * BATCH + b) * HID + h] = rate * (1.f / 300.f);
}

// ============================================================
// Head: outs = relu(rates @ fc_w + fc_b); out = cat @ w_out + b_out
// ============================================================
__global__ void head_kernel(const float* __restrict__ fc_w,
                            const float* __restrict__ fc_b,
                            const float* __restrict__ w_out,
                            const float* __restrict__ b_out,
                            float* __restrict__ dout) {
    const int b = blockIdx.x;
    const int h = threadIdx.x;  // 128 threads
    __shared__ float rs[4][128];
    __shared__ float cat[512];

#pragma unroll
    for (int l = 0; l < 4; l++) rs[l][h] = g_rates[(l * BATCH + b) * HID + h];
    __syncthreads();

#pragma unroll
    for (int l = 0; l < 4; l++) {
        float acc = fc_b[l * HID + h];
        const float* W = fc_w + (size_t)l * HID * HID;
#pragma unroll 8
        for (int k = 0; k < HID; k++) acc += rs[l][k] * W[(size_t)k * HID + h];
        cat[l * HID + h] = fmaxf(acc, 0.f);
    }
    __syncthreads();

    if (h < OUTD) {
        float acc = b_out[h];
#pragma unroll 8
        for (int k = 0; k < 4 * HID; k++) acc += cat[k] * w_out[(size_t)k * OUTD + h];
        dout[OUT_OFF + b * OUTD + h] = acc;
    }
}

// ============================================================
// A_norm = sum |A_w|
// ============================================================
__global__ void norm_kernel(const float* __restrict__ Aw, float* __restrict__ dout) {
    __shared__ float s[256];
    float acc = 0.f;
    for (int i = threadIdx.x; i < LAYERS * HID * HID; i += 256) acc += fabsf(Aw[i]);
    s[threadIdx.x] = acc;
    __syncthreads();
    for (int st = 128; st > 0; st >>= 1) {
        if (threadIdx.x < st) s[threadIdx.x] += s[threadIdx.x + st];
        __syncthreads();
    }
    if (threadIdx.x == 0) dout[NORM_OFF] = s[0];
}

// ============================================================
extern "C" void kernel_launch(void* const* d_in, const int* in_sizes, int n_in,
                              void* d_out, int out_size) {
    const float* x     = (const float*)d_in[0];
    const float* w_in  = (const float*)d_in[1];
    const float* b_in  = (const float*)d_in[2];
    const float* A_w   = (const float*)d_in[3];
    const float* A_b   = (const float*)d_in[4];
    const float* fc_w  = (const float*)d_in[5];
    const float* fc_b  = (const float*)d_in[6];
    const float* w_out = (const float*)d_in[7];
    const float* b_out = (const float*)d_in[8];
    const float* thr   = (const float*)d_in[9];
    const float* decay = (const float*)d_in[10];
    const float* rst   = (const float*)d_in[11];
    const float* mem0  = (const float*)d_in[12];
    float* out = (float*)d_out;

    gemm_in<<<M_TOTAL / 128, 256>>>(x, w_in, b_in);

    dim3 g2(M_TOTAL / 128, LAYERS);
    gemm_res<<<g2, 256>>>(A_w, A_b);

    dim3 g3(BATCH, LAYERS);
    scan_kernel<<<g3, 128>>>(mem0, thr, decay, rst, out);

    head_kernel<<<BATCH, 128>>>(fc_w, fc_b, w_out, b_out, out);
    norm_kernel<<<1, 256>>>(A_w, out);
}

// round 2
// speedup vs baseline: 1.0798x; 1.0798x over previous
#include <cuda_runtime.h>

// ---------------- problem constants ----------------
#define T_STEPS 300
#define BATCH   256
#define HID     128
#define D_IN    700
#define LAYERS  4
#define OUTD    20
#define M_TOTAL (T_STEPS * BATCH)   // 76800

// output buffer layout (tuple concatenated, fp32)
#define OUT_OFF  0
#define MEM_OFF  (BATCH * OUTD)                            // 5120
#define SPK_OFF  (MEM_OFF + BATCH * (T_STEPS + 1) * HID)   // 9866248
#define NORM_OFF (SPK_OFF + BATCH * (T_STEPS + 1) * HID)   // 19727376

// ---------------- scratch (device globals; no allocations) ----------------
__device__ float g_inp[M_TOTAL * HID];                     // [T][B][H]
__device__ float g_xs[(size_t)LAYERS * M_TOTAL * HID];     // [L][T*B][H]
__device__ float g_rates[LAYERS * BATCH * HID];

// ---------------- packed fp32x2 helpers ----------------
typedef unsigned long long ull;
__device__ __forceinline__ void fma2(ull& c, ull a, ull b) {
    asm("fma.rn.f32x2 %0, %1, %2, %0;" : "+l"(c) : "l"(a), "l"(b));
}
__device__ __forceinline__ ull dup2(float x) {
    ull r;
    asm("mov.b64 %0, {%1, %2};" : "=l"(r) : "f"(x), "f"(x));
    return r;
}
__device__ __forceinline__ float2 unpack2(ull v) {
    float2 f;
    asm("mov.b64 {%0, %1}, %2;" : "=f"(f.x), "=f"(f.y) : "l"(v));
    return f;
}

// ============================================================
// GEMM core config: BM=256, BN=128, BK=8, 256 threads.
// Thread tile 16m x 8n  (8 m-pairs as f32x2 x 8 n) = 64 fma2/kk.
// Double-buffered smem, register prefetch, 1 sync per k-tile.
// Per-accumulator k order is ascending (bit-identical to round 1).
// ============================================================

// GEMM1: inp[t*256+b][h] = sum_d x[(b*300+t)][d] * w_in[d][h] + b_in[h]
__global__ __launch_bounds__(256, 1) void gemm_in(const float* __restrict__ x,
                                                  const float* __restrict__ w,
                                                  const float* __restrict__ bias) {
    __shared__ float As[2][8][256];
    __shared__ float Bs[2][8][128];
    const int tid = threadIdx.x;
    const int m0 = blockIdx.x * 256;
    const int tx = tid & 15, tym = tid >> 4;

    const float* xr = x + (size_t)(m0 + tid) * D_IN;
    const int kb = tid >> 5;
    const int nb = (tid & 31) * 4;

    ull acc[8][8];
#pragma unroll
    for (int p = 0; p < 8; p++)
#pragma unroll
        for (int j = 0; j < 8; j++) acc[p][j] = 0ull;

    const float4 zero4 = make_float4(0.f, 0.f, 0.f, 0.f);

    // prologue: tile 0 (k0 = 0, fully valid)
    {
        float4 a0 = *(const float4*)(xr + 0);
        float4 a1 = *(const float4*)(xr + 4);
        As[0][0][tid] = a0.x; As[0][1][tid] = a0.y; As[0][2][tid] = a0.z; As[0][3][tid] = a0.w;
        As[0][4][tid] = a1.x; As[0][5][tid] = a1.y; As[0][6][tid] = a1.z; As[0][7][tid] = a1.w;
        float4 b = *(const float4*)(w + (size_t)kb * HID + nb);
        *(float4*)&Bs[0][kb][nb] = b;
    }
    __syncthreads();

    const int NT = (D_IN + 7) / 8;  // 88
    for (int t = 0; t < NT; t++) {
        const int cur = t & 1;
        const int k0n = (t + 1) * 8;
        const bool more = (t + 1) < NT;
        float4 na0 = zero4, na1 = zero4, nb4 = zero4;
        if (more) {
            na0 = *(const float4*)(xr + k0n);                       // k0n..k0n+3 < 700 always
            if (k0n + 7 < D_IN) na1 = *(const float4*)(xr + k0n + 4);
            if (k0n + kb < D_IN) nb4 = *(const float4*)(w + (size_t)(k0n + kb) * HID + nb);
        }

#pragma unroll
        for (int kk = 0; kk < 8; kk++) {
            const ull* Ap = (const ull*)&As[cur][kk][tym * 16];
            ull a2[8];
#pragma unroll
            for (int p = 0; p < 8; p++) a2[p] = Ap[p];
            const float4* Bp = (const float4*)&Bs[cur][kk][tx * 8];
            float4 b0 = Bp[0], b1 = Bp[1];
            ull b2[8];
            b2[0] = dup2(b0.x); b2[1] = dup2(b0.y); b2[2] = dup2(b0.z); b2[3] = dup2(b0.w);
            b2[4] = dup2(b1.x); b2[5] = dup2(b1.y); b2[6] = dup2(b1.z); b2[7] = dup2(b1.w);
#pragma unroll
            for (int p = 0; p < 8; p++)
#pragma unroll
                for (int j = 0; j < 8; j++) fma2(acc[p][j], a2[p], b2[j]);
        }

        if (more) {
            const int nxt = cur ^ 1;
            As[nxt][0][tid] = na0.x; As[nxt][1][tid] = na0.y; As[nxt][2][tid] = na0.z; As[nxt][3][tid] = na0.w;
            As[nxt][4][tid] = na1.x; As[nxt][5][tid] = na1.y; As[nxt][6][tid] = na1.z; As[nxt][7][tid] = na1.w;
            *(float4*)&Bs[nxt][kb][nb] = nb4;
        }
        __syncthreads();
    }

    float bb[8];
#pragma unroll
    for (int j = 0; j < 8; j++) bb[j] = bias[tx * 8 + j];

#pragma unroll
    for (int p = 0; p < 8; p++) {
        float lo[8], hi[8];
#pragma unroll
        for (int j = 0; j < 8; j++) {
            float2 v = unpack2(acc[p][j]);
            lo[j] = v.x + bb[j];
            hi[j] = v.y + bb[j];
        }
        const int m_lo = m0 + tym * 16 + 2 * p;
        {
            int b_ = m_lo / T_STEPS, t_ = m_lo % T_STEPS;
            float* o = g_inp + (size_t)(t_ * BATCH + b_) * HID + tx * 8;
            *(float4*)o = make_float4(lo[0], lo[1], lo[2], lo[3]);
            *(float4*)(o + 4) = make_float4(lo[4], lo[5], lo[6], lo[7]);
        }
        {
            int m_hi = m_lo + 1;
            int b_ = m_hi / T_STEPS, t_ = m_hi % T_STEPS;
            float* o = g_inp + (size_t)(t_ * BATCH + b_) * HID + tx * 8;
            *(float4*)o = make_float4(hi[0], hi[1], hi[2], hi[3]);
            *(float4*)(o + 4) = make_float4(hi[4], hi[5], hi[6], hi[7]);
        }
    }
}

// GEMM2: xs[l][m][n] = sum_k inp[m][k] * A_w[l][k][n] + A_b[l][n]
__global__ __launch_bounds__(256, 1) void gemm_res(const float* __restrict__ Aw,
                                                   const float* __restrict__ Ab) {
    __shared__ float As[2][8][256];
    __shared__ float Bs[2][8][128];
    const int tid = threadIdx.x;
    const int m0 = blockIdx.x * 256;
    const int l = blockIdx.y;
    const int tx = tid & 15, tym = tid >> 4;

    const float* w = Aw + (size_t)l * HID * HID;
    float* out = g_xs + (size_t)l * M_TOTAL * HID;
    const float* ar = g_inp + (size_t)(m0 + tid) * HID;
    const int kb = tid >> 5;
    const int nb = (tid & 31) * 4;

    ull acc[8][8];
#pragma unroll
    for (int p = 0; p < 8; p++)
#pragma unroll
        for (int j = 0; j < 8; j++) acc[p][j] = 0ull;

    {
        float4 a0 = *(const float4*)(ar + 0);
        float4 a1 = *(const float4*)(ar + 4);
        As[0][0][tid] = a0.x; As[0][1][tid] = a0.y; As[0][2][tid] = a0.z; As[0][3][tid] = a0.w;
        As[0][4][tid] = a1.x; As[0][5][tid] = a1.y; As[0][6][tid] = a1.z; As[0][7][tid] = a1.w;
        float4 b = *(const float4*)(w + (size_t)kb * HID + nb);
        *(float4*)&Bs[0][kb][nb] = b;
    }
    __syncthreads();

    const int NT = HID / 8;  // 16
    for (int t = 0; t < NT; t++) {
        const int cur = t & 1;
        const int k0n = (t + 1) * 8;
        const bool more = (t + 1) < NT;
        float4 na0, na1, nb4;
        if (more) {
            na0 = *(const float4*)(ar + k0n);
            na1 = *(const float4*)(ar + k0n + 4);
            nb4 = *(const float4*)(w + (size_t)(k0n + kb) * HID + nb);
        }

#pragma unroll
        for (int kk = 0; kk < 8; kk++) {
            const ull* Ap = (const ull*)&As[cur][kk][tym * 16];
            ull a2[8];
#pragma unroll
            for (int p = 0; p < 8; p++) a2[p] = Ap[p];
            const float4* Bp = (const float4*)&Bs[cur][kk][tx * 8];
            float4 b0 = Bp[0], b1 = Bp[1];
            ull b2[8];
            b2[0] = dup2(b0.x); b2[1] = dup2(b0.y); b2[2] = dup2(b0.z); b2[3] = dup2(b0.w);
            b2[4] = dup2(b1.x); b2[5] = dup2(b1.y); b2[6] = dup2(b1.z); b2[7] = dup2(b1.w);
#pragma unroll
            for (int p = 0; p < 8; p++)
#pragma unroll
                for (int j = 0; j < 8; j++) fma2(acc[p][j], a2[p], b2[j]);
        }

        if (more) {
            const int nxt = cur ^ 1;
            As[nxt][0][tid] = na0.x; As[nxt][1][tid] = na0.y; As[nxt][2][tid] = na0.z; As[nxt][3][tid] = na0.w;
            As[nxt][4][tid] = na1.x; As[nxt][5][tid] = na1.y; As[nxt][6][tid] = na1.z; As[nxt][7][tid] = na1.w;
            *(float4*)&Bs[nxt][kb][nb] = nb4;
        }
        __syncthreads();
    }

    float bb[8];
#pragma unroll
    for (int j = 0; j < 8; j++) bb[j] = Ab[l * HID + tx * 8 + j];

#pragma unroll
    for (int p = 0; p < 8; p++) {
        float lo[8], hi[8];
#pragma unroll
        for (int j = 0; j < 8; j++) {
            float2 v = unpack2(acc[p][j]);
            lo[j] = v.x + bb[j];
            hi[j] = v.y + bb[j];
        }
        const int m_lo = m0 + tym * 16 + 2 * p;
        float* o0 = out + (size_t)m_lo * HID + tx * 8;
        *(float4*)o0 = make_float4(lo[0], lo[1], lo[2], lo[3]);
        *(float4*)(o0 + 4) = make_float4(lo[4], lo[5], lo[6], lo[7]);
        float* o1 = out + (size_t)(m_lo + 1) * HID + tx * 8;
        *(float4*)o1 = make_float4(hi[0], hi[1], hi[2], hi[3]);
        *(float4*)(o1 + 4) = make_float4(hi[4], hi[5], hi[6], hi[7]);
    }
}

// ============================================================
// Sequential LIF scan over T. block = (b, l), thread = neuron h.
// ============================================================
__global__ void scan_kernel(const float* __restrict__ mem0,
                            const float* __restrict__ thr,
                            const float* __restrict__ decay,
                            const float* __restrict__ rstv,
                            float* __restrict__ dout) {
    const int b = blockIdx.x;
    const int l = blockIdx.y;
    const int h = threadIdx.x;

    const float* xp = g_xs + (size_t)l * M_TOTAL * HID + (size_t)b * HID + h;
    float mem = mem0[(l * BATCH + b) * HID + h];
    float spk = 0.f, rate = 0.f;
    const float th = thr[h], dc = decay[h], rs = rstv[h];
    const bool last = (l == 3);

    float* mo = dout + MEM_OFF + (size_t)b * (T_STEPS + 1) * HID + h;
    float* so = dout + SPK_OFF + (size_t)b * (T_STEPS + 1) * HID + h;
    if (last) { mo[0] = mem; so[0] = 0.f; }

    const int ST = BATCH * HID;
    for (int t = 0; t < T_STEPS; t += 10) {
        float v[10];
#pragma unroll
        for (int j = 0; j < 10; j++) v[j] = xp[(size_t)(t + j) * ST];
#pragma unroll
        for (int j = 0; j < 10; j++) {
            mem = rs * spk + mem * dc * (1.f - spk) + v[j];
            spk = (mem - th > 0.f) ? 1.f : 0.f;
            rate += spk;
            if (last) {
                mo[(size_t)(t + j + 1) * HID] = mem;
                so[(size_t)(t + j + 1) * HID] = spk;
            }
        }
    }
    g_rates[(l * BATCH + b) * HID + h] = rate * (1.f / 300.f);
}

// ============================================================
// Head (rewritten): block per batch, 640 threads.
//   stage1: threads 0..511 = (l,h), 4-way ILP over k.
//   stage2: warp w (w<20) computes out[b][w] via shuffle reduce.
// ============================================================
__global__ __launch_bounds__(640) void head_kernel(const float* __restrict__ fc_w,
                                                   const float* __restrict__ fc_b,
                                                   const float* __restrict__ w_out,
                                                   const float* __restrict__ b_out,
                                                   float* __restrict__ dout) {
    const int b = blockIdx.x;
    const int tid = threadIdx.x;
    __shared__ float rs[512];
    __shared__ float cat[512];

    if (tid < 512) {
        int l = tid >> 7, h = tid & 127;
        rs[tid] = g_rates[(l * BATCH + b) * HID + h];
    }
    __syncthreads();

    if (tid < 512) {
        int l = tid >> 7, h = tid & 127;
        const float* W = fc_w + (size_t)l * HID * HID + h;
        const float* r = &rs[l * HID];
        float a0 = 0.f, a1 = 0.f, a2 = 0.f, a3 = 0.f;
#pragma unroll
        for (int k = 0; k < HID; k += 4) {
            a0 += r[k + 0] * W[(size_t)(k + 0) * HID];
            a1 += r[k + 1] * W[(size_t)(k + 1) * HID];
            a2 += r[k + 2] * W[(size_t)(k + 2) * HID];
            a3 += r[k + 3] * W[(size_t)(k + 3) * HID];
        }
        float acc = ((a0 + a1) + (a2 + a3)) + fc_b[l * HID + h];
        cat[tid] = fmaxf(acc, 0.f);
    }
    __syncthreads();

    const int w = tid >> 5, lane = tid & 31;
    if (w < OUTD) {
        float acc = 0.f;
#pragma unroll
        for (int k = lane; k < 512; k += 32) acc += cat[k] * w_out[(size_t)k * OUTD + w];
#pragma unroll
        for (int off = 16; off; off >>= 1) acc += __shfl_down_sync(0xffffffffu, acc, off);
        if (lane == 0) dout[OUT_OFF + b * OUTD + w] = acc + b_out[w];
    }
}

// ============================================================
// A_norm = sum |A_w|
// ============================================================
__global__ void norm_kernel(const float* __restrict__ Aw, float* __restrict__ dout) {
    __shared__ float s[256];
    float acc = 0.f;
    const float4* A4 = (const float4*)Aw;
    const int N4 = LAYERS * HID * HID / 4;
    for (int i = threadIdx.x; i < N4; i += 256) {
        float4 v = A4[i];
        acc += fabsf(v.x) + fabsf(v.y) + fabsf(v.z) + fabsf(v.w);
    }
    s[threadIdx.x] = acc;
    __syncthreads();
    for (int st = 128; st > 0; st >>= 1) {
        if (threadIdx.x < st) s[threadIdx.x] += s[threadIdx.x + st];
        __syncthreads();
    }
    if (threadIdx.x == 0) dout[NORM_OFF] = s[0];
}

// ============================================================
extern "C" void kernel_launch(void* const* d_in, const int* in_sizes, int n_in,
                              void* d_out, int out_size) {
    const float* x     = (const float*)d_in[0];
    const float* w_in  = (const float*)d_in[1];
    const float* b_in  = (const float*)d_in[2];
    const float* A_w   = (const float*)d_in[3];
    const float* A_b   = (const float*)d_in[4];
    const float* fc_w  = (const float*)d_in[5];
    const float* fc_b  = (const float*)d_in[6];
    const float* w_out = (const float*)d_in[7];
    const float* b_out = (const float*)d_in[8];
    const float* thr   = (const float*)d_in[9];
    const float* decay = (const float*)d_in[10];
    const float* rst   = (const float*)d_in[11];
    const float* mem0  = (const float*)d_in[12];
    float* out = (float*)d_out;

    gemm_in<<<M_TOTAL / 256, 256>>>(x, w_in, b_in);

    dim3 g2(M_TOTAL / 256, LAYERS);
    gemm_res<<<g2, 256>>>(A_w, A_b);

    dim3 g3(BATCH, LAYERS);
    scan_kernel<<<g3, 128>>>(mem0, thr, decay, rst, out);

    head_kernel<<<BATCH, 640>>>(fc_w, fc_b, w_out, b_out, out);
    norm_kernel<<<1, 256>>>(A_w, out);
}

// round 6
// speedup vs baseline: 1.3405x; 1.2415x over previous
#include <cuda_runtime.h>
#include <cuda_fp16.h>
#include <cstdint>

// ---------------- problem constants ----------------
#define T_STEPS 300
#define BATCH   256
#define HID     128
#define D_IN    700
#define KPAD    704
#define LAYERS  4
#define OUTD    20
#define M_TOTAL (T_STEPS * BATCH)   // 76800

#define OUT_OFF  0
#define MEM_OFF  (BATCH * OUTD)
#define SPK_OFF  (MEM_OFF + BATCH * (T_STEPS + 1) * HID)
#define NORM_OFF (SPK_OFF + BATCH * (T_STEPS + 1) * HID)

// ---------------- scratch (device globals; no allocations) ----------------
__device__ float g_xs[(size_t)LAYERS * M_TOTAL * HID];
__device__ float g_rates[LAYERS * BATCH * HID];
// presplit weights (scaled x32), [comp][n][k]
__device__ __align__(16) __half g_wsplit[3][HID][KPAD];
__device__ __align__(16) __half g_asplit[3][LAYERS][HID][HID];
// 3-comp split of (inp*32), [m][k] per comp
__device__ __align__(16) __half g_ic0[(size_t)M_TOTAL * HID];
__device__ __align__(16) __half g_ic1[(size_t)M_TOTAL * HID];
__device__ __align__(16) __half g_ic2[(size_t)M_TOTAL * HID];

// ---------------- smem tile geometry ----------------
#define ROWB    80
#define CSTRIDE (128 * ROWB)
#define BOFF    (3 * CSTRIDE)
#define BUFSZ   (6 * CSTRIDE)
#define GEMM_SMEM (2 * BUFSZ)

// ---------------- helpers ----------------
__device__ __forceinline__ uint32_t smem_u32(const void* p) {
    uint32_t a;
    asm("{ .reg .u64 t; cvta.to.shared.u64 t, %1; cvt.u32.u64 %0, t; }" : "=r"(a) : "l"(p));
    return a;
}
__device__ __forceinline__ void ldsm4(uint32_t* d, uint32_t addr) {
    asm volatile("ldmatrix.sync.aligned.m8n8.x4.shared.b16 {%0,%1,%2,%3}, [%4];"
                 : "=r"(d[0]), "=r"(d[1]), "=r"(d[2]), "=r"(d[3]) : "r"(addr));
}
__device__ __forceinline__ void mma16816(float* d, const uint32_t* a, const uint32_t* b) {
    asm volatile(
        "mma.sync.aligned.m16n8k16.row.col.f32.f16.f16.f32 "
        "{%0,%1,%2,%3}, {%4,%5,%6,%7}, {%8,%9}, {%0,%1,%2,%3};"
        : "+f"(d[0]), "+f"(d[1]), "+f"(d[2]), "+f"(d[3])
        : "r"(a[0]), "r"(a[1]), "r"(a[2]), "r"(a[3]), "r"(b[0]), "r"(b[1]));
}
__device__ __forceinline__ void cpa16(uint32_t s, const void* g) {
    asm volatile("cp.async.cg.shared.global [%0], [%1], 16;" :: "r"(s), "l"(g));
}
__device__ __forceinline__ void cpa_wait_all() {
    asm volatile("cp.async.wait_all;" ::: "memory");
}
// exact 3-way fp16 split
__device__ __forceinline__ void split3(float v, __half& c0, __half& c1, __half& c2) {
    c0 = __float2half_rn(v);
    float r0 = v - __half2float(c0);
    c1 = __float2half_rn(r0);
    c2 = __float2half_rn(r0 - __half2float(c1));
}

// ============================================================
// presplit: w_in and A_w -> 3 fp16 comps (x32), transposed to [n][k]
// ============================================================
__global__ __launch_bounds__(256) void presplit(const float* __restrict__ w_in,
                                                const float* __restrict__ Aw) {
    int i = blockIdx.x * 256 + threadIdx.x;
    if (i < HID * KPAD) {
        int n = i / KPAD, k = i % KPAD;
        float v = (k < D_IN) ? w_in[(size_t)k * HID + n] * 32.f : 0.f;
        __half a, b, c;
        split3(v, a, b, c);
        g_wsplit[0][n][k] = a; g_wsplit[1][n][k] = b; g_wsplit[2][n][k] = c;
    }
    if (i < LAYERS * HID * HID) {
        int l = i >> 14, rem = i & 16383, n = rem >> 7, k = rem & 127;
        float v = Aw[(size_t)l * HID * HID + (size_t)k * HID + n] * 32.f;
        __half a, b, c;
        split3(v, a, b, c);
        g_asplit[0][l][n][k] = a; g_asplit[1][l][n][k] = b; g_asplit[2][l][n][k] = c;
    }
}

// ============================================================
// MMA core, split accumulators:
//   accA += a0*b0            (full-magnitude pass)
//   accB += a0*b1 + a0*b2 + a1*b0 + a1*b1 + a2*b0   (corrections)
// ============================================================
__device__ __forceinline__ void tile_mma(float (&accA)[4][4][4], float (&accB)[4][4][4],
                                         uint32_t Ab, uint32_t Bb,
                                         uint32_t a_lane, uint32_t b_lane) {
#pragma unroll
    for (int ks = 0; ks < 2; ks++) {
        uint32_t bf[3][4][2];
#pragma unroll
        for (int c = 0; c < 3; c++)
#pragma unroll
            for (int np = 0; np < 2; np++) {
                uint32_t r4[4];
                ldsm4(r4, Bb + (uint32_t)(c * CSTRIDE + np * 16 * ROWB + ks * 32) + b_lane);
                bf[c][np * 2 + 0][0] = r4[0]; bf[c][np * 2 + 0][1] = r4[1];
                bf[c][np * 2 + 1][0] = r4[2]; bf[c][np * 2 + 1][1] = r4[3];
            }
        uint32_t af[4][4];
        // A comp 0: b0 -> accA ; b1, b2 -> accB
#pragma unroll
        for (int mf = 0; mf < 4; mf++)
            ldsm4(af[mf], Ab + (uint32_t)(0 * CSTRIDE + mf * 16 * ROWB + ks * 32) + a_lane);
#pragma unroll
        for (int mf = 0; mf < 4; mf++)
#pragma unroll
            for (int nf = 0; nf < 4; nf++) mma16816(accA[mf][nf], af[mf], bf[0][nf]);
#pragma unroll
        for (int cb = 1; cb < 3; cb++)
#pragma unroll
            for (int mf = 0; mf < 4; mf++)
#pragma unroll
                for (int nf = 0; nf < 4; nf++) mma16816(accB[mf][nf], af[mf], bf[cb][nf]);
        // A comp 1: b0, b1 -> accB
#pragma unroll
        for (int mf = 0; mf < 4; mf++)
            ldsm4(af[mf], Ab + (uint32_t)(1 * CSTRIDE + mf * 16 * ROWB + ks * 32) + a_lane);
#pragma unroll
        for (int cb = 0; cb < 2; cb++)
#pragma unroll
            for (int mf = 0; mf < 4; mf++)
#pragma unroll
                for (int nf = 0; nf < 4; nf++) mma16816(accB[mf][nf], af[mf], bf[cb][nf]);
        // A comp 2: b0 -> accB
#pragma unroll
        for (int mf = 0; mf < 4; mf++)
            ldsm4(af[mf], Ab + (uint32_t)(2 * CSTRIDE + mf * 16 * ROWB + ks * 32) + a_lane);
#pragma unroll
        for (int mf = 0; mf < 4; mf++)
#pragma unroll
            for (int nf = 0; nf < 4; nf++) mma16816(accB[mf][nf], af[mf], bf[0][nf]);
    }
}

__device__ __forceinline__ void store_inp_split2(int row, int col, float a, float b) {
    size_t idx = (size_t)row * HID + col;
    a *= 32.f; b *= 32.f;
    __half a0, a1, a2, b0, b1, b2;
    split3(a, a0, a1, a2);
    split3(b, b0, b1, b2);
    *(__half2*)(g_ic0 + idx) = __halves2half2(a0, b0);
    *(__half2*)(g_ic1 + idx) = __halves2half2(a1, b1);
    *(__half2*)(g_ic2 + idx) = __halves2half2(a2, b2);
}

// ============================================================
// GEMM1: inp = x @ w_in + b_in ; epilogue stores 3-comp split of inp*32
// ============================================================
__global__ __launch_bounds__(256, 1) void gemm1(const float* __restrict__ x,
                                                const float* __restrict__ b_in) {
    extern __shared__ char smem[];
    const uint32_t sb = smem_u32(smem);
    const int tid = threadIdx.x, lane = tid & 31, wid = tid >> 5;
    const int wm = wid & 1, wn = wid >> 1;
    const int m0 = blockIdx.x * 128;
    const int q = lane >> 3, r = lane & 7;
    const uint32_t a_lane = (uint32_t)((wm * 64 + (q & 1) * 8 + r) * ROWB + ((q >> 1) * 8) * 2);
    const uint32_t b_lane = (uint32_t)((wn * 32 + (q >> 1) * 8 + r) * ROWB + ((q & 1) * 8) * 2);

    float accA[4][4][4], accB[4][4][4];
#pragma unroll
    for (int i = 0; i < 4; i++)
#pragma unroll
        for (int j = 0; j < 4; j++)
#pragma unroll
            for (int k = 0; k < 4; k++) { accA[i][j][k] = 0.f; accB[i][j][k] = 0.f; }

    auto stage = [&](int t, int buf) {
        const int k0 = t * 32;
        char* Abp = smem + buf * BUFSZ;
        const uint32_t Bb = sb + (uint32_t)(buf * BUFSZ + BOFF);
#pragma unroll
        for (int i = 0; i < 2; i++) {
            int g = tid + i * 256;
            int row = g >> 2, kg = (g & 3) * 8;
            int k = k0 + kg;
            const float* p = x + (size_t)(m0 + row) * D_IN + k;
            float4 u0 = *(const float4*)p;
            float4 u1 = (k + 4 < D_IN) ? *(const float4*)(p + 4)
                                       : make_float4(0.f, 0.f, 0.f, 0.f);
            float v[8] = {u0.x, u0.y, u0.z, u0.w, u1.x, u1.y, u1.z, u1.w};
            __align__(16) __half h0[8], h1[8], h2[8];
#pragma unroll
            for (int j = 0; j < 8; j++) split3(v[j] * 32.f, h0[j], h1[j], h2[j]);
            char* d = Abp + row * ROWB + kg * 2;
            *(uint4*)(d + 0 * CSTRIDE) = *(uint4*)h0;
            *(uint4*)(d + 1 * CSTRIDE) = *(uint4*)h1;
            *(uint4*)(d + 2 * CSTRIDE) = *(uint4*)h2;
        }
#pragma unroll
        for (int c = 0; c < 3; c++)
#pragma unroll
            for (int i = 0; i < 2; i++) {
                int idx = tid + i * 256;
                int n = idx >> 2, ch = idx & 3;
                cpa16(Bb + (uint32_t)(c * CSTRIDE + n * ROWB + ch * 16),
                      &g_wsplit[c][n][k0 + ch * 8]);
            }
    };

    stage(0, 0);
    cpa_wait_all();
    __syncthreads();
    for (int t = 0; t < 22; t++) {
        if (t + 1 < 22) stage(t + 1, (t + 1) & 1);
        const uint32_t base = sb + (uint32_t)((t & 1) * BUFSZ);
        tile_mma(accA, accB, base, base + BOFF, a_lane, b_lane);
        cpa_wait_all();
        __syncthreads();
    }

    const float inv = 1.0f / 1024.0f;
#pragma unroll
    for (int mf = 0; mf < 4; mf++) {
        const int row0 = m0 + wm * 64 + mf * 16 + (lane >> 2);
#pragma unroll
        for (int nf = 0; nf < 4; nf++) {
            const int col = wn * 32 + nf * 8 + (lane & 3) * 2;
            const float bb0 = b_in[col], bb1 = b_in[col + 1];
            store_inp_split2(row0, col,
                             (accA[mf][nf][0] + accB[mf][nf][0]) * inv + bb0,
                             (accA[mf][nf][1] + accB[mf][nf][1]) * inv + bb1);
            store_inp_split2(row0 + 8, col,
                             (accA[mf][nf][2] + accB[mf][nf][2]) * inv + bb0,
                             (accA[mf][nf][3] + accB[mf][nf][3]) * inv + bb1);
        }
    }
}

// ============================================================
// GEMM2: xs[l] = inp @ A_w[l] + A_b[l]  — pure cp.async staging
// ============================================================
__global__ __launch_bounds__(256, 1) void gemm2(const float* __restrict__ Abias) {
    extern __shared__ char smem[];
    const uint32_t sb = smem_u32(smem);
    const int tid = threadIdx.x, lane = tid & 31, wid = tid >> 5;
    const int wm = wid & 1, wn = wid >> 1;
    const int m0 = blockIdx.x * 128;
    const int l = blockIdx.y;
    const int q = lane >> 3, r = lane & 7;
    const uint32_t a_lane = (uint32_t)((wm * 64 + (q & 1) * 8 + r) * ROWB + ((q >> 1) * 8) * 2);
    const uint32_t b_lane = (uint32_t)((wn * 32 + (q >> 1) * 8 + r) * ROWB + ((q & 1) * 8) * 2);

    float accA[4][4][4], accB[4][4][4];
#pragma unroll
    for (int i = 0; i < 4; i++)
#pragma unroll
        for (int j = 0; j < 4; j++)
#pragma unroll
            for (int k = 0; k < 4; k++) { accA[i][j][k] = 0.f; accB[i][j][k] = 0.f; }

    auto stage = [&](int t, int buf) {
        const int k0 = t * 32;
        const uint32_t Ab = sb + (uint32_t)(buf * BUFSZ);
        const uint32_t Bb = Ab + BOFF;
#pragma unroll
        for (int c = 0; c < 3; c++) {
            const __half* base = (c == 0) ? g_ic0 : (c == 1) ? g_ic1 : g_ic2;
#pragma unroll
            for (int i = 0; i < 2; i++) {
                int idx = tid + i * 256;
                int row = idx >> 2, ch = idx & 3;
                cpa16(Ab + (uint32_t)(c * CSTRIDE + row * ROWB + ch * 16),
                      base + (size_t)(m0 + row) * HID + k0 + ch * 8);
            }
#pragma unroll
            for (int i = 0; i < 2; i++) {
                int idx = tid + i * 256;
                int n = idx >> 2, ch = idx & 3;
                cpa16(Bb + (uint32_t)(c * CSTRIDE + n * ROWB + ch * 16),
                      &g_asplit[c][l][n][k0 + ch * 8]);
            }
        }
    };

    stage(0, 0);
    cpa_wait_all();
    __syncthreads();
    for (int t = 0; t < 4; t++) {
        if (t + 1 < 4) stage(t + 1, (t + 1) & 1);
        const uint32_t base = sb + (uint32_t)((t & 1) * BUFSZ);
        tile_mma(accA, accB, base, base + BOFF, a_lane, b_lane);
        cpa_wait_all();
        __syncthreads();
    }

    float* dst = g_xs + (size_t)l * M_TOTAL * HID;
    const float inv = 1.0f / 1024.0f;
#pragma unroll
    for (int mf = 0; mf < 4; mf++) {
        const int row0 = m0 + wm * 64 + mf * 16 + (lane >> 2);
#pragma unroll
        for (int nf = 0; nf < 4; nf++) {
            const int col = wn * 32 + nf * 8 + (lane & 3) * 2;
            const float bb0 = Abias[l * HID + col], bb1 = Abias[l * HID + col + 1];
            *(float2*)(dst + (size_t)row0 * HID + col) =
                make_float2((accA[mf][nf][0] + accB[mf][nf][0]) * inv + bb0,
                            (accA[mf][nf][1] + accB[mf][nf][1]) * inv + bb1);
            *(float2*)(dst + (size_t)(row0 + 8) * HID + col) =
                make_float2((accA[mf][nf][2] + accB[mf][nf][2]) * inv + bb0,
                            (accA[mf][nf][3] + accB[mf][nf][3]) * inv + bb1);
        }
    }
}

// ============================================================
// Sequential LIF scan. block=(b,l), thread=h.
// ============================================================
__global__ void scan_kernel(const float* __restrict__ mem0,
                            const float* __restrict__ thr,
                            const float* __restrict__ decay,
                            const float* __restrict__ rstv,
                            float* __restrict__ dout) {
    const int b = blockIdx.x;
    const int l = blockIdx.y;
    const int h = threadIdx.x;

    const float* xp = g_xs + (size_t)l * M_TOTAL * HID + (size_t)b * T_STEPS * HID + h;
    float mem = mem0[(l * BATCH + b) * HID + h];
    float spk = 0.f, rate = 0.f;
    const float th = thr[h], dc = decay[h], rs = rstv[h];
    const bool last = (l == 3);

    float* mo = dout + MEM_OFF + (size_t)b * (T_STEPS + 1) * HID + h;
    float* so = dout + SPK_OFF + (size_t)b * (T_STEPS + 1) * HID + h;
    if (last) { mo[0] = mem; so[0] = 0.f; }

    for (int t = 0; t < T_STEPS; t += 10) {
        float v[10];
#pragma unroll
        for (int j = 0; j < 10; j++) v[j] = xp[(size_t)(t + j) * HID];
#pragma unroll
        for (int j = 0; j < 10; j++) {
            mem = rs * spk + mem * dc * (1.f - spk) + v[j];
            spk = (mem - th > 0.f) ? 1.f : 0.f;
            rate += spk;
            if (last) {
                mo[(size_t)(t + j + 1) * HID] = mem;
                so[(size_t)(t + j + 1) * HID] = spk;
            }
        }
    }
    g_rates[(l * BATCH + b) * HID + h] = rate * (1.f / 300.f);
}

// ============================================================
// Head: block per batch, 640 threads.
// ============================================================
__global__ __launch_bounds__(640) void head_kernel(const float* __restrict__ fc_w,
                                                   const float* __restrict__ fc_b,
                                                   const float* __restrict__ w_out,
                                                   const float* __restrict__ b_out,
                                                   float* __restrict__ dout) {
    const int b = blockIdx.x;
    const int tid = threadIdx.x;
    __shared__ float rs[512];
    __shared__ float cat[512];

    if (tid < 512) {
        int l = tid >> 7, h = tid & 127;
        rs[tid] = g_rates[(l * BATCH + b) * HID + h];
    }
    __syncthreads();

    if (tid < 512) {
        int l = tid >> 7, h = tid & 127;
        const float* W = fc_w + (size_t)l * HID * HID + h;
        const float* rr = &rs[l * HID];
        float a0 = 0.f, a1 = 0.f, a2 = 0.f, a3 = 0.f;
#pragma unroll
        for (int k = 0; k < HID; k += 4) {
            a0 += rr[k + 0] * W[(size_t)(k + 0) * HID];
            a1 += rr[k + 1] * W[(size_t)(k + 1) * HID];
            a2 += rr[k + 2] * W[(size_t)(k + 2) * HID];
            a3 += rr[k + 3] * W[(size_t)(k + 3) * HID];
        }
        float acc = ((a0 + a1) + (a2 + a3)) + fc_b[l * HID + h];
        cat[tid] = fmaxf(acc, 0.f);
    }
    __syncthreads();

    const int w = tid >> 5, lane = tid & 31;
    if (w < OUTD) {
        float acc = 0.f;
#pragma unroll
        for (int k = lane; k < 512; k += 32) acc += cat[k] * w_out[(size_t)k * OUTD + w];
#pragma unroll
        for (int off = 16; off; off >>= 1) acc += __shfl_down_sync(0xffffffffu, acc, off);
        if (lane == 0) dout[OUT_OFF + b * OUTD + w] = acc + b_out[w];
    }
}

// ============================================================
// A_norm = sum |A_w|
// ============================================================
__global__ __launch_bounds__(1024) void norm_kernel(const float* __restrict__ Aw,
                                                    float* __restrict__ dout) {
    __shared__ float s[1024];
    float acc = 0.f;
    const float4* A4 = (const float4*)Aw;
    const int N4 = LAYERS * HID * HID / 4;
    for (int i = threadIdx.x; i < N4; i += 1024) {
        float4 v = A4[i];
        acc += fabsf(v.x) + fabsf(v.y) + fabsf(v.z) + fabsf(v.w);
    }
    s[threadIdx.x] = acc;
    __syncthreads();
    for (int st = 512; st > 0; st >>= 1) {
        if (threadIdx.x < st) s[threadIdx.x] += s[threadIdx.x + st];
        __syncthreads();
    }
    if (threadIdx.x == 0) dout[NORM_OFF] = s[0];
}

// ============================================================
extern "C" void kernel_launch(void* const* d_in, const int* in_sizes, int n_in,
                              void* d_out, int out_size) {
    const float* x     = (const float*)d_in[0];
    const float* w_in  = (const float*)d_in[1];
    const float* b_in  = (const float*)d_in[2];
    const float* A_w   = (const float*)d_in[3];
    const float* A_b   = (const float*)d_in[4];
    const float* fc_w  = (const float*)d_in[5];
    const float* fc_b  = (const float*)d_in[6];
    const float* w_out = (const float*)d_in[7];
    const float* b_out = (const float*)d_in[8];
    const float* thr   = (const float*)d_in[9];
    const float* decay = (const float*)d_in[10];
    const float* rst   = (const float*)d_in[11];
    const float* mem0  = (const float*)d_in[12];
    float* out = (float*)d_out;

    cudaFuncSetAttribute(gemm1, cudaFuncAttributeMaxDynamicSharedMemorySize, GEMM_SMEM);
    cudaFuncSetAttribute(gemm2, cudaFuncAttributeMaxDynamicSharedMemorySize, GEMM_SMEM);

    presplit<<<(HID * KPAD + 255) / 256, 256>>>(w_in, A_w);

    gemm1<<<M_TOTAL / 128, 256, GEMM_SMEM>>>(x, b_in);

    dim3 g2(M_TOTAL / 128, LAYERS);
    gemm2<<<g2, 256, GEMM_SMEM>>>(A_b);

    dim3 g3(BATCH, LAYERS);
    scan_kernel<<<g3, 128>>>(mem0, thr, decay, rst, out);

    head_kernel<<<BATCH, 640>>>(fc_w, fc_b, w_out, b_out, out);
    norm_kernel<<<1, 1024>>>(A_w, out);
}

// round 7
// speedup vs baseline: 1.5026x; 1.1209x over previous
#include <cuda_runtime.h>
#include <cuda_fp16.h>
#include <cstdint>

// ---------------- problem constants ----------------
#define T_STEPS 300
#define BATCH   256
#define HID     128
#define D_IN    700
#define KPAD    704
#define LAYERS  4
#define OUTD    20
#define M_TOTAL (T_STEPS * BATCH)   // 76800

#define OUT_OFF  0
#define MEM_OFF  (BATCH * OUTD)
#define SPK_OFF  (MEM_OFF + BATCH * (T_STEPS + 1) * HID)
#define NORM_OFF (SPK_OFF + BATCH * (T_STEPS + 1) * HID)

// ---------------- scratch (device globals; no allocations) ----------------
__device__ float g_xs[(size_t)LAYERS * M_TOTAL * HID];
__device__ float g_rates[LAYERS * BATCH * HID];
// presplit weights (scaled x32), [comp][n][k]
__device__ __align__(16) __half g_wsplit[3][HID][KPAD];
__device__ __align__(16) __half g_asplit[3][LAYERS][HID][HID];
// 3-comp split of (inp*32), [m][k] per comp
__device__ __align__(16) __half g_ic0[(size_t)M_TOTAL * HID];
__device__ __align__(16) __half g_ic1[(size_t)M_TOTAL * HID];
__device__ __align__(16) __half g_ic2[(size_t)M_TOTAL * HID];

// ---------------- smem tile geometry ----------------
#define ROWB    80
#define CSTRIDE (128 * ROWB)       // 10240 bytes per comp per 32-k tile
#define ATILE   (3 * CSTRIDE)      // 30720: one 3-comp operand tile
#define BUFSZ   (2 * ATILE)        // A(3)+B(3) for gemm1 stage
#define GEMM1_SMEM (2 * BUFSZ)     // 122880
#define GEMM2_SMEM (6 * ATILE)     // 184320: A-resident(4) + B double buffer(2)

// ---------------- helpers ----------------
__device__ __forceinline__ uint32_t smem_u32(const void* p) {
    uint32_t a;
    asm("{ .reg .u64 t; cvta.to.shared.u64 t, %1; cvt.u32.u64 %0, t; }" : "=r"(a) : "l"(p));
    return a;
}
__device__ __forceinline__ void ldsm4(uint32_t* d, uint32_t addr) {
    asm volatile("ldmatrix.sync.aligned.m8n8.x4.shared.b16 {%0,%1,%2,%3}, [%4];"
                 : "=r"(d[0]), "=r"(d[1]), "=r"(d[2]), "=r"(d[3]) : "r"(addr));
}
__device__ __forceinline__ void mma16816(float* d, const uint32_t* a, const uint32_t* b) {
    asm volatile(
        "mma.sync.aligned.m16n8k16.row.col.f32.f16.f16.f32 "
        "{%0,%1,%2,%3}, {%4,%5,%6,%7}, {%8,%9}, {%0,%1,%2,%3};"
        : "+f"(d[0]), "+f"(d[1]), "+f"(d[2]), "+f"(d[3])
        : "r"(a[0]), "r"(a[1]), "r"(a[2]), "r"(a[3]), "r"(b[0]), "r"(b[1]));
}
__device__ __forceinline__ void cpa16(uint32_t s, const void* g) {
    asm volatile("cp.async.cg.shared.global [%0], [%1], 16;" :: "r"(s), "l"(g));
}
__device__ __forceinline__ void cpa_wait_all() {
    asm volatile("cp.async.wait_all;" ::: "memory");
}
// exact 3-way fp16 split
__device__ __forceinline__ void split3(float v, __half& c0, __half& c1, __half& c2) {
    c0 = __float2half_rn(v);
    float r0 = v - __half2float(c0);
    c1 = __float2half_rn(r0);
    c2 = __float2half_rn(r0 - __half2float(c1));
}

// ============================================================
// presplit: w_in and A_w -> 3 fp16 comps (x32), transposed to [n][k]
// ============================================================
__global__ __launch_bounds__(256) void presplit(const float* __restrict__ w_in,
                                                const float* __restrict__ Aw) {
    int i = blockIdx.x * 256 + threadIdx.x;
    if (i < HID * KPAD) {
        int n = i / KPAD, k = i % KPAD;
        float v = (k < D_IN) ? w_in[(size_t)k * HID + n] * 32.f : 0.f;
        __half a, b, c;
        split3(v, a, b, c);
        g_wsplit[0][n][k] = a; g_wsplit[1][n][k] = b; g_wsplit[2][n][k] = c;
    }
    if (i < LAYERS * HID * HID) {
        int l = i >> 14, rem = i & 16383, n = rem >> 7, k = rem & 127;
        float v = Aw[(size_t)l * HID * HID + (size_t)k * HID + n] * 32.f;
        __half a, b, c;
        split3(v, a, b, c);
        g_asplit[0][l][n][k] = a; g_asplit[1][l][n][k] = b; g_asplit[2][l][n][k] = c;
    }
}

// ============================================================
// MMA core, split accumulators (accA = main pass, accB = corrections)
// ============================================================
__device__ __forceinline__ void tile_mma(float (&accA)[4][4][4], float (&accB)[4][4][4],
                                         uint32_t Ab, uint32_t Bb,
                                         uint32_t a_lane, uint32_t b_lane) {
#pragma unroll
    for (int ks = 0; ks < 2; ks++) {
        uint32_t bf[3][4][2];
#pragma unroll
        for (int c = 0; c < 3; c++)
#pragma unroll
            for (int np = 0; np < 2; np++) {
                uint32_t r4[4];
                ldsm4(r4, Bb + (uint32_t)(c * CSTRIDE + np * 16 * ROWB + ks * 32) + b_lane);
                bf[c][np * 2 + 0][0] = r4[0]; bf[c][np * 2 + 0][1] = r4[1];
                bf[c][np * 2 + 1][0] = r4[2]; bf[c][np * 2 + 1][1] = r4[3];
            }
        uint32_t af[4][4];
#pragma unroll
        for (int mf = 0; mf < 4; mf++)
            ldsm4(af[mf], Ab + (uint32_t)(0 * CSTRIDE + mf * 16 * ROWB + ks * 32) + a_lane);
#pragma unroll
        for (int mf = 0; mf < 4; mf++)
#pragma unroll
            for (int nf = 0; nf < 4; nf++) mma16816(accA[mf][nf], af[mf], bf[0][nf]);
#pragma unroll
        for (int cb = 1; cb < 3; cb++)
#pragma unroll
            for (int mf = 0; mf < 4; mf++)
#pragma unroll
                for (int nf = 0; nf < 4; nf++) mma16816(accB[mf][nf], af[mf], bf[cb][nf]);
#pragma unroll
        for (int mf = 0; mf < 4; mf++)
            ldsm4(af[mf], Ab + (uint32_t)(1 * CSTRIDE + mf * 16 * ROWB + ks * 32) + a_lane);
#pragma unroll
        for (int cb = 0; cb < 2; cb++)
#pragma unroll
            for (int mf = 0; mf < 4; mf++)
#pragma unroll
                for (int nf = 0; nf < 4; nf++) mma16816(accB[mf][nf], af[mf], bf[cb][nf]);
#pragma unroll
        for (int mf = 0; mf < 4; mf++)
            ldsm4(af[mf], Ab + (uint32_t)(2 * CSTRIDE + mf * 16 * ROWB + ks * 32) + a_lane);
#pragma unroll
        for (int mf = 0; mf < 4; mf++)
#pragma unroll
            for (int nf = 0; nf < 4; nf++) mma16816(accB[mf][nf], af[mf], bf[0][nf]);
    }
}

__device__ __forceinline__ void store_inp_split2(int row, int col, float a, float b) {
    size_t idx = (size_t)row * HID + col;
    a *= 32.f; b *= 32.f;
    __half a0, a1, a2, b0, b1, b2;
    split3(a, a0, a1, a2);
    split3(b, b0, b1, b2);
    *(__half2*)(g_ic0 + idx) = __halves2half2(a0, b0);
    *(__half2*)(g_ic1 + idx) = __halves2half2(a1, b1);
    *(__half2*)(g_ic2 + idx) = __halves2half2(a2, b2);
}

// ============================================================
// GEMM1: inp = x @ w_in + b_in ; register-staged pipeline:
//   LDG x(t+1) issued BEFORE mma(t); convert+STS after mma(t).
// ============================================================
__global__ __launch_bounds__(256, 1) void gemm1(const float* __restrict__ x,
                                                const float* __restrict__ b_in) {
    extern __shared__ char smem[];
    const uint32_t sb = smem_u32(smem);
    const int tid = threadIdx.x, lane = tid & 31, wid = tid >> 5;
    const int wm = wid & 1, wn = wid >> 1;
    const int m0 = blockIdx.x * 128;
    const int q = lane >> 3, r = lane & 7;
    const uint32_t a_lane = (uint32_t)((wm * 64 + (q & 1) * 8 + r) * ROWB + ((q >> 1) * 8) * 2);
    const uint32_t b_lane = (uint32_t)((wn * 32 + (q >> 1) * 8 + r) * ROWB + ((q & 1) * 8) * 2);

    float accA[4][4][4], accB[4][4][4];
#pragma unroll
    for (int i = 0; i < 4; i++)
#pragma unroll
        for (int j = 0; j < 4; j++)
#pragma unroll
            for (int k = 0; k < 4; k++) { accA[i][j][k] = 0.f; accB[i][j][k] = 0.f; }

    float4 u0[2], u1[2];

    auto load_x = [&](int t) {
        const int k0 = t * 32;
#pragma unroll
        for (int i = 0; i < 2; i++) {
            int g = tid + i * 256;
            int row = g >> 2, kg = (g & 3) * 8;
            int k = k0 + kg;
            const float* p = x + (size_t)(m0 + row) * D_IN + k;
            u0[i] = *(const float4*)p;
            u1[i] = (k + 4 < D_IN) ? *(const float4*)(p + 4)
                                   : make_float4(0.f, 0.f, 0.f, 0.f);
        }
    };
    auto store_A = [&](int buf) {
        char* Abp = smem + buf * BUFSZ;
#pragma unroll
        for (int i = 0; i < 2; i++) {
            int g = tid + i * 256;
            int row = g >> 2, kg = (g & 3) * 8;
            float v[8] = {u0[i].x, u0[i].y, u0[i].z, u0[i].w,
                          u1[i].x, u1[i].y, u1[i].z, u1[i].w};
            __align__(16) __half h0[8], h1[8], h2[8];
#pragma unroll
            for (int j = 0; j < 8; j++) split3(v[j] * 32.f, h0[j], h1[j], h2[j]);
            char* d = Abp + row * ROWB + kg * 2;
            *(uint4*)(d + 0 * CSTRIDE) = *(uint4*)h0;
            *(uint4*)(d + 1 * CSTRIDE) = *(uint4*)h1;
            *(uint4*)(d + 2 * CSTRIDE) = *(uint4*)h2;
        }
    };
    auto issue_B = [&](int t, int buf) {
        const int k0 = t * 32;
        const uint32_t Bb = sb + (uint32_t)(buf * BUFSZ + ATILE);
#pragma unroll
        for (int c = 0; c < 3; c++)
#pragma unroll
            for (int i = 0; i < 2; i++) {
                int idx = tid + i * 256;
                int n = idx >> 2, ch = idx & 3;
                cpa16(Bb + (uint32_t)(c * CSTRIDE + n * ROWB + ch * 16),
                      &g_wsplit[c][n][k0 + ch * 8]);
            }
    };

    // prologue: tile 0
    load_x(0);
    store_A(0);
    issue_B(0, 0);
    cpa_wait_all();
    __syncthreads();

    for (int t = 0; t < 22; t++) {
        const bool more = (t + 1) < 22;
        if (more) {
            load_x(t + 1);              // LDGs in flight during mma
            issue_B(t + 1, (t + 1) & 1);
        }
        const uint32_t base = sb + (uint32_t)((t & 1) * BUFSZ);
        tile_mma(accA, accB, base, base + ATILE, a_lane, b_lane);
        if (more) store_A((t + 1) & 1); // convert after mma; LDG latency hidden
        cpa_wait_all();
        __syncthreads();
    }

    const float inv = 1.0f / 1024.0f;
#pragma unroll
    for (int mf = 0; mf < 4; mf++) {
        const int row0 = m0 + wm * 64 + mf * 16 + (lane >> 2);
#pragma unroll
        for (int nf = 0; nf < 4; nf++) {
            const int col = wn * 32 + nf * 8 + (lane & 3) * 2;
            const float bb0 = b_in[col], bb1 = b_in[col + 1];
            store_inp_split2(row0, col,
                             (accA[mf][nf][0] + accB[mf][nf][0]) * inv + bb0,
                             (accA[mf][nf][1] + accB[mf][nf][1]) * inv + bb1);
            store_inp_split2(row0 + 8, col,
                             (accA[mf][nf][2] + accB[mf][nf][2]) * inv + bb0,
                             (accA[mf][nf][3] + accB[mf][nf][3]) * inv + bb1);
        }
    }
}

// ============================================================
// GEMM2 (A-resident): block = m-tile; stage all 4 A k-tiles once,
// loop 4 layers x 4 k-tiles with B double-buffered from L2.
// ============================================================
__global__ __launch_bounds__(256, 1) void gemm2(const float* __restrict__ Abias) {
    extern __shared__ char smem[];
    const uint32_t sb = smem_u32(smem);
    const int tid = threadIdx.x, lane = tid & 31, wid = tid >> 5;
    const int wm = wid & 1, wn = wid >> 1;
    const int m0 = blockIdx.x * 128;
    const int q = lane >> 3, r = lane & 7;
    const uint32_t a_lane = (uint32_t)((wm * 64 + (q & 1) * 8 + r) * ROWB + ((q >> 1) * 8) * 2);
    const uint32_t b_lane = (uint32_t)((wn * 32 + (q >> 1) * 8 + r) * ROWB + ((q & 1) * 8) * 2);
    const uint32_t Bbase = sb + 4u * ATILE;

    float accA[4][4][4], accB[4][4][4];
#pragma unroll
    for (int i = 0; i < 4; i++)
#pragma unroll
        for (int j = 0; j < 4; j++)
#pragma unroll
            for (int k = 0; k < 4; k++) { accA[i][j][k] = 0.f; accB[i][j][k] = 0.f; }

    auto stage_B = [&](int l, int kt, int buf) {
        const int k0 = kt * 32;
        const uint32_t Bb = Bbase + (uint32_t)(buf * ATILE);
#pragma unroll
        for (int c = 0; c < 3; c++)
#pragma unroll
            for (int i = 0; i < 2; i++) {
                int idx = tid + i * 256;
                int n = idx >> 2, ch = idx & 3;
                cpa16(Bb + (uint32_t)(c * CSTRIDE + n * ROWB + ch * 16),
                      &g_asplit[c][l][n][k0 + ch * 8]);
            }
    };

    // stage ALL A tiles (resident for whole kernel)
#pragma unroll
    for (int kt = 0; kt < 4; kt++) {
        const uint32_t Ab = sb + (uint32_t)(kt * ATILE);
        const int k0 = kt * 32;
#pragma unroll
        for (int c = 0; c < 3; c++) {
            const __half* base = (c == 0) ? g_ic0 : (c == 1) ? g_ic1 : g_ic2;
#pragma unroll
            for (int i = 0; i < 2; i++) {
                int idx = tid + i * 256;
                int row = idx >> 2, ch = idx & 3;
                cpa16(Ab + (uint32_t)(c * CSTRIDE + row * ROWB + ch * 16),
                      base + (size_t)(m0 + row) * HID + k0 + ch * 8);
            }
        }
    }
    stage_B(0, 0, 0);
    cpa_wait_all();
    __syncthreads();

    const float inv = 1.0f / 1024.0f;
    for (int s = 0; s < 16; s++) {
        const int l = s >> 2, kt = s & 3;
        if (s + 1 < 16) stage_B((s + 1) >> 2, (s + 1) & 3, (s + 1) & 1);
        tile_mma(accA, accB, sb + (uint32_t)(kt * ATILE),
                 Bbase + (uint32_t)((s & 1) * ATILE), a_lane, b_lane);
        if (kt == 3) {
            float* dst = g_xs + (size_t)l * M_TOTAL * HID;
#pragma unroll
            for (int mf = 0; mf < 4; mf++) {
                const int row0 = m0 + wm * 64 + mf * 16 + (lane >> 2);
#pragma unroll
                for (int nf = 0; nf < 4; nf++) {
                    const int col = wn * 32 + nf * 8 + (lane & 3) * 2;
                    const float bb0 = Abias[l * HID + col];
                    const float bb1 = Abias[l * HID + col + 1];
                    *(float2*)(dst + (size_t)row0 * HID + col) =
                        make_float2((accA[mf][nf][0] + accB[mf][nf][0]) * inv + bb0,
                                    (accA[mf][nf][1] + accB[mf][nf][1]) * inv + bb1);
                    *(float2*)(dst + (size_t)(row0 + 8) * HID + col) =
                        make_float2((accA[mf][nf][2] + accB[mf][nf][2]) * inv + bb0,
                                    (accA[mf][nf][3] + accB[mf][nf][3]) * inv + bb1);
                }
            }
#pragma unroll
            for (int i = 0; i < 4; i++)
#pragma unroll
                for (int j = 0; j < 4; j++)
#pragma unroll
                    for (int k = 0; k < 4; k++) { accA[i][j][k] = 0.f; accB[i][j][k] = 0.f; }
        }
        cpa_wait_all();
        __syncthreads();
    }
}

// ============================================================
// Sequential LIF scan. block=(b,l), thread=h.
// ============================================================
__global__ void scan_kernel(const float* __restrict__ mem0,
                            const float* __restrict__ thr,
                            const float* __restrict__ decay,
                            const float* __restrict__ rstv,
                            float* __restrict__ dout) {
    const int b = blockIdx.x;
    const int l = blockIdx.y;
    const int h = threadIdx.x;

    const float* xp = g_xs + (size_t)l * M_TOTAL * HID + (size_t)b * T_STEPS * HID + h;
    float mem = mem0[(l * BATCH + b) * HID + h];
    float spk = 0.f, rate = 0.f;
    const float th = thr[h], dc = decay[h], rs = rstv[h];
    const bool last = (l == 3);

    float* mo = dout + MEM_OFF + (size_t)b * (T_STEPS + 1) * HID + h;
    float* so = dout + SPK_OFF + (size_t)b * (T_STEPS + 1) * HID + h;
    if (last) { mo[0] = mem; so[0] = 0.f; }

    for (int t = 0; t < T_STEPS; t += 10) {
        float v[10];
#pragma unroll
        for (int j = 0; j < 10; j++) v[j] = xp[(size_t)(t + j) * HID];
#pragma unroll
        for (int j = 0; j < 10; j++) {
            mem = rs * spk + mem * dc * (1.f - spk) + v[j];
            spk = (mem - th > 0.f) ? 1.f : 0.f;
            rate += spk;
            if (last) {
                mo[(size_t)(t + j + 1) * HID] = mem;
                so[(size_t)(t + j + 1) * HID] = spk;
            }
        }
    }
    g_rates[(l * BATCH + b) * HID + h] = rate * (1.f / 300.f);
}

// ============================================================
// Head: block per batch, 640 threads.
// ============================================================
__global__ __launch_bounds__(640) void head_kernel(const float* __restrict__ fc_w,
                                                   const float* __restrict__ fc_b,
                                                   const float* __restrict__ w_out,
                                                   const float* __restrict__ b_out,
                                                   float* __restrict__ dout) {
    const int b = blockIdx.x;
    const int tid = threadIdx.x;
    __shared__ float rs[512];
    __shared__ float cat[512];

    if (tid < 512) {
        int l = tid >> 7, h = tid & 127;
        rs[tid] = g_rates[(l * BATCH + b) * HID + h];
    }
    __syncthreads();

    if (tid < 512) {
        int l = tid >> 7, h = tid & 127;
        const float* W = fc_w + (size_t)l * HID * HID + h;
        const float* rr = &rs[l * HID];
        float a0 = 0.f, a1 = 0.f, a2 = 0.f, a3 = 0.f;
#pragma unroll
        for (int k = 0; k < HID; k += 4) {
            a0 += rr[k + 0] * W[(size_t)(k + 0) * HID];
            a1 += rr[k + 1] * W[(size_t)(k + 1) * HID];
            a2 += rr[k + 2] * W[(size_t)(k + 2) * HID];
            a3 += rr[k + 3] * W[(size_t)(k + 3) * HID];
        }
        float acc = ((a0 + a1) + (a2 + a3)) + fc_b[l * HID + h];
        cat[tid] = fmaxf(acc, 0.f);
    }
    __syncthreads();

    const int w = tid >> 5, lane = tid & 31;
    if (w < OUTD) {
        float acc = 0.f;
#pragma unroll
        for (int k = lane; k < 512; k += 32) acc += cat[k] * w_out[(size_t)k * OUTD + w];
#pragma unroll
        for (int off = 16; off; off >>= 1) acc += __shfl_down_sync(0xffffffffu, acc, off);
        if (lane == 0) dout[OUT_OFF + b * OUTD + w] = acc + b_out[w];
    }
}

// ============================================================
// A_norm = sum |A_w|
// ============================================================
__global__ __launch_bounds__(1024) void norm_kernel(const float* __restrict__ Aw,
                                                    float* __restrict__ dout) {
    __shared__ float s[1024];
    float acc = 0.f;
    const float4* A4 = (const float4*)Aw;
    const int N4 = LAYERS * HID * HID / 4;
    for (int i = threadIdx.x; i < N4; i += 1024) {
        float4 v = A4[i];
        acc += fabsf(v.x) + fabsf(v.y) + fabsf(v.z) + fabsf(v.w);
    }
    s[threadIdx.x] = acc;
    __syncthreads();
    for (int st = 512; st > 0; st >>= 1) {
        if (threadIdx.x < st) s[threadIdx.x] += s[threadIdx.x + st];
        __syncthreads();
    }
    if (threadIdx.x == 0) dout[NORM_OFF] = s[0];
}

// ============================================================
extern "C" void kernel_launch(void* const* d_in, const int* in_sizes, int n_in,
                              void* d_out, int out_size) {
    const float* x     = (const float*)d_in[0];
    const float* w_in  = (const float*)d_in[1];
    const float* b_in  = (const float*)d_in[2];
    const float* A_w   = (const float*)d_in[3];
    const float* A_b   = (const float*)d_in[4];
    const float* fc_w  = (const float*)d_in[5];
    const float* fc_b  = (const float*)d_in[6];
    const float* w_out = (const float*)d_in[7];
    const float* b_out = (const float*)d_in[8];
    const float* thr   = (const float*)d_in[9];
    const float* decay = (const float*)d_in[10];
    const float* rst   = (const float*)d_in[11];
    const float* mem0  = (const float*)d_in[12];
    float* out = (float*)d_out;

    cudaFuncSetAttribute(gemm1, cudaFuncAttributeMaxDynamicSharedMemorySize, GEMM1_SMEM);
    cudaFuncSetAttribute(gemm2, cudaFuncAttributeMaxDynamicSharedMemorySize, GEMM2_SMEM);

    presplit<<<(HID * KPAD + 255) / 256, 256>>>(w_in, A_w);

    gemm1<<<M_TOTAL / 128, 256, GEMM1_SMEM>>>(x, b_in);

    gemm2<<<M_TOTAL / 128, 256, GEMM2_SMEM>>>(A_b);

    dim3 g3(BATCH, LAYERS);
    scan_kernel<<<g3, 128>>>(mem0, thr, decay, rst, out);

    head_kernel<<<BATCH, 640>>>(fc_w, fc_b, w_out, b_out, out);
    norm_kernel<<<1, 1024>>>(A_w, out);
}

// round 8
// speedup vs baseline: 1.5990x; 1.0642x over previous
#include <cuda_runtime.h>
#include <cuda_fp16.h>
#include <cstdint>

// ---------------- problem constants ----------------
#define T_STEPS 300
#define BATCH   256
#define HID     128
#define D_IN    700
#define KPAD    704
#define LAYERS  4
#define OUTD    20
#define M_TOTAL (T_STEPS * BATCH)   // 76800

#define OUT_OFF  0
#define MEM_OFF  (BATCH * OUTD)
#define SPK_OFF  (MEM_OFF + BATCH * (T_STEPS + 1) * HID)
#define NORM_OFF (SPK_OFF + BATCH * (T_STEPS + 1) * HID)

// ---------------- scratch (device globals; no allocations) ----------------
__device__ float g_xs[(size_t)LAYERS * M_TOTAL * HID];
__device__ float g_rates[LAYERS * BATCH * HID];
// presplit weights (scaled x32), [comp][n][k]
__device__ __align__(16) __half g_wsplit[3][HID][KPAD];
__device__ __align__(16) __half g_asplit[3][LAYERS][HID][HID];

// ---------------- smem tile geometry ----------------
#define ROWB    80
#define CSTRIDE (128 * ROWB)       // 10240 bytes per comp per 32-k tile
#define ATILE   (3 * CSTRIDE)      // 30720: one 3-comp operand tile
#define BUFSZ   (2 * ATILE)        // phase-1 stage buffer: A(3)+B(3)
// phase-2 A-resident region (4 k-tiles) overlays phase-1's two stage buffers
#define B2OFF   (4 * ATILE)        // 122880
#define FUSED_SMEM (6 * ATILE)     // 184320

// ---------------- helpers ----------------
__device__ __forceinline__ uint32_t smem_u32(const void* p) {
    uint32_t a;
    asm("{ .reg .u64 t; cvta.to.shared.u64 t, %1; cvt.u32.u64 %0, t; }" : "=r"(a) : "l"(p));
    return a;
}
__device__ __forceinline__ void ldsm4(uint32_t* d, uint32_t addr) {
    asm volatile("ldmatrix.sync.aligned.m8n8.x4.shared.b16 {%0,%1,%2,%3}, [%4];"
                 : "=r"(d[0]), "=r"(d[1]), "=r"(d[2]), "=r"(d[3]) : "r"(addr));
}
__device__ __forceinline__ void mma16816(float* d, const uint32_t* a, const uint32_t* b) {
    asm volatile(
        "mma.sync.aligned.m16n8k16.row.col.f32.f16.f16.f32 "
        "{%0,%1,%2,%3}, {%4,%5,%6,%7}, {%8,%9}, {%0,%1,%2,%3};"
        : "+f"(d[0]), "+f"(d[1]), "+f"(d[2]), "+f"(d[3])
        : "r"(a[0]), "r"(a[1]), "r"(a[2]), "r"(a[3]), "r"(b[0]), "r"(b[1]));
}
__device__ __forceinline__ void cpa16(uint32_t s, const void* g) {
    asm volatile("cp.async.cg.shared.global [%0], [%1], 16;" :: "r"(s), "l"(g));
}
__device__ __forceinline__ void cpa_wait_all() {
    asm volatile("cp.async.wait_all;" ::: "memory");
}
// exact 3-way fp16 split
__device__ __forceinline__ void split3(float v, __half& c0, __half& c1, __half& c2) {
    c0 = __float2half_rn(v);
    float r0 = v - __half2float(c0);
    c1 = __float2half_rn(r0);
    c2 = __float2half_rn(r0 - __half2float(c1));
}

// ============================================================
// presplit: w_in and A_w -> 3 fp16 comps (x32), transposed to [n][k]
// ============================================================
__global__ __launch_bounds__(256) void presplit(const float* __restrict__ w_in,
                                                const float* __restrict__ Aw) {
    int i = blockIdx.x * 256 + threadIdx.x;
    if (i < HID * KPAD) {
        int n = i / KPAD, k = i % KPAD;
        float v = (k < D_IN) ? w_in[(size_t)k * HID + n] * 32.f : 0.f;
        __half a, b, c;
        split3(v, a, b, c);
        g_wsplit[0][n][k] = a; g_wsplit[1][n][k] = b; g_wsplit[2][n][k] = c;
    }
    if (i < LAYERS * HID * HID) {
        int l = i >> 14, rem = i & 16383, n = rem >> 7, k = rem & 127;
        float v = Aw[(size_t)l * HID * HID + (size_t)k * HID + n] * 32.f;
        __half a, b, c;
        split3(v, a, b, c);
        g_asplit[0][l][n][k] = a; g_asplit[1][l][n][k] = b; g_asplit[2][l][n][k] = c;
    }
}

// ============================================================
// MMA core, split accumulators (accA = main pass, accB = corrections)
// ============================================================
__device__ __forceinline__ void tile_mma(float (&accA)[4][4][4], float (&accB)[4][4][4],
                                         uint32_t Ab, uint32_t Bb,
                                         uint32_t a_lane, uint32_t b_lane) {
#pragma unroll
    for (int ks = 0; ks < 2; ks++) {
        uint32_t bf[3][4][2];
#pragma unroll
        for (int c = 0; c < 3; c++)
#pragma unroll
            for (int np = 0; np < 2; np++) {
                uint32_t r4[4];
                ldsm4(r4, Bb + (uint32_t)(c * CSTRIDE + np * 16 * ROWB + ks * 32) + b_lane);
                bf[c][np * 2 + 0][0] = r4[0]; bf[c][np * 2 + 0][1] = r4[1];
                bf[c][np * 2 + 1][0] = r4[2]; bf[c][np * 2 + 1][1] = r4[3];
            }
        uint32_t af[4][4];
#pragma unroll
        for (int mf = 0; mf < 4; mf++)
            ldsm4(af[mf], Ab + (uint32_t)(0 * CSTRIDE + mf * 16 * ROWB + ks * 32) + a_lane);
#pragma unroll
        for (int mf = 0; mf < 4; mf++)
#pragma unroll
            for (int nf = 0; nf < 4; nf++) mma16816(accA[mf][nf], af[mf], bf[0][nf]);
#pragma unroll
        for (int cb = 1; cb < 3; cb++)
#pragma unroll
            for (int mf = 0; mf < 4; mf++)
#pragma unroll
                for (int nf = 0; nf < 4; nf++) mma16816(accB[mf][nf], af[mf], bf[cb][nf]);
#pragma unroll
        for (int mf = 0; mf < 4; mf++)
            ldsm4(af[mf], Ab + (uint32_t)(1 * CSTRIDE + mf * 16 * ROWB + ks * 32) + a_lane);
#pragma unroll
        for (int cb = 0; cb < 2; cb++)
#pragma unroll
            for (int mf = 0; mf < 4; mf++)
#pragma unroll
                for (int nf = 0; nf < 4; nf++) mma16816(accB[mf][nf], af[mf], bf[cb][nf]);
#pragma unroll
        for (int mf = 0; mf < 4; mf++)
            ldsm4(af[mf], Ab + (uint32_t)(2 * CSTRIDE + mf * 16 * ROWB + ks * 32) + a_lane);
#pragma unroll
        for (int mf = 0; mf < 4; mf++)
#pragma unroll
            for (int nf = 0; nf < 4; nf++) mma16816(accB[mf][nf], af[mf], bf[0][nf]);
    }
}

// ============================================================
// FUSED GEMM: per 128-row m-tile:
//   phase 1: inp = x @ w_in + b_in (22 k-tiles, split-fp16 HMMA)
//   epilogue: split3(inp*32) written DIRECTLY into phase-2 smem A layout
//   phase 2: xs[l] = inp @ A_w[l] + A_b[l], 4 layers x 4 k-tiles, B dbl-buffered
// ============================================================
__global__ __launch_bounds__(256, 1) void gemm_fused(const float* __restrict__ x,
                                                     const float* __restrict__ b_in,
                                                     const float* __restrict__ Abias) {
    extern __shared__ char smem[];
    const uint32_t sb = smem_u32(smem);
    const int tid = threadIdx.x, lane = tid & 31, wid = tid >> 5;
    const int wm = wid & 1, wn = wid >> 1;
    const int m0 = blockIdx.x * 128;
    const int q = lane >> 3, r = lane & 7;
    const uint32_t a_lane = (uint32_t)((wm * 64 + (q & 1) * 8 + r) * ROWB + ((q >> 1) * 8) * 2);
    const uint32_t b_lane = (uint32_t)((wn * 32 + (q >> 1) * 8 + r) * ROWB + ((q & 1) * 8) * 2);

    float accA[4][4][4], accB[4][4][4];
#pragma unroll
    for (int i = 0; i < 4; i++)
#pragma unroll
        for (int j = 0; j < 4; j++)
#pragma unroll
            for (int k = 0; k < 4; k++) { accA[i][j][k] = 0.f; accB[i][j][k] = 0.f; }

    // ---------------- phase 1 ----------------
    float4 u0[2], u1[2];
    auto load_x = [&](int t) {
        const int k0 = t * 32;
#pragma unroll
        for (int i = 0; i < 2; i++) {
            int g = tid + i * 256;
            int row = g >> 2, kg = (g & 3) * 8;
            int k = k0 + kg;
            const float* p = x + (size_t)(m0 + row) * D_IN + k;
            u0[i] = *(const float4*)p;
            u1[i] = (k + 4 < D_IN) ? *(const float4*)(p + 4)
                                   : make_float4(0.f, 0.f, 0.f, 0.f);
        }
    };
    auto store_A = [&](int buf) {
        char* Abp = smem + buf * BUFSZ;
#pragma unroll
        for (int i = 0; i < 2; i++) {
            int g = tid + i * 256;
            int row = g >> 2, kg = (g & 3) * 8;
            float v[8] = {u0[i].x, u0[i].y, u0[i].z, u0[i].w,
                          u1[i].x, u1[i].y, u1[i].z, u1[i].w};
            __align__(16) __half h0[8], h1[8], h2[8];
#pragma unroll
            for (int j = 0; j < 8; j++) split3(v[j] * 32.f, h0[j], h1[j], h2[j]);
            char* d = Abp + row * ROWB + kg * 2;
            *(uint4*)(d + 0 * CSTRIDE) = *(uint4*)h0;
            *(uint4*)(d + 1 * CSTRIDE) = *(uint4*)h1;
            *(uint4*)(d + 2 * CSTRIDE) = *(uint4*)h2;
        }
    };
    auto issue_B = [&](int t, int buf) {
        const int k0 = t * 32;
        const uint32_t Bb = sb + (uint32_t)(buf * BUFSZ + ATILE);
#pragma unroll
        for (int c = 0; c < 3; c++)
#pragma unroll
            for (int i = 0; i < 2; i++) {
                int idx = tid + i * 256;
                int n = idx >> 2, ch = idx & 3;
                cpa16(Bb + (uint32_t)(c * CSTRIDE + n * ROWB + ch * 16),
                      &g_wsplit[c][n][k0 + ch * 8]);
            }
    };

    load_x(0);
    store_A(0);
    issue_B(0, 0);
    cpa_wait_all();
    __syncthreads();

    for (int t = 0; t < 22; t++) {
        const bool more = (t + 1) < 22;
        if (more) {
            load_x(t + 1);
            issue_B(t + 1, (t + 1) & 1);
        }
        const uint32_t base = sb + (uint32_t)((t & 1) * BUFSZ);
        tile_mma(accA, accB, base, base + ATILE, a_lane, b_lane);
        if (more) store_A((t + 1) & 1);
        cpa_wait_all();
        __syncthreads();
    }

    // ---------------- phase-2 B staging helper ----------------
    auto stage_B2 = [&](int l, int kt, int buf) {
        const int k0 = kt * 32;
        const uint32_t Bb = sb + (uint32_t)(B2OFF + buf * ATILE);
#pragma unroll
        for (int c = 0; c < 3; c++)
#pragma unroll
            for (int i = 0; i < 2; i++) {
                int idx = tid + i * 256;
                int n = idx >> 2, ch = idx & 3;
                cpa16(Bb + (uint32_t)(c * CSTRIDE + n * ROWB + ch * 16),
                      &g_asplit[c][l][n][k0 + ch * 8]);
            }
    };

    // prefetch first phase-2 B tile (B2 region is untouched by phase 1)
    stage_B2(0, 0, 0);

    // ---------------- epilogue: split inp directly into phase-2 A layout ----
    // (phase-1 staging buffers are dead; they become the A-resident region)
    {
        const float inv = 1.0f / 1024.0f;
#pragma unroll
        for (int mf = 0; mf < 4; mf++) {
            const int row0 = wm * 64 + mf * 16 + (lane >> 2);  // local row
#pragma unroll
            for (int nf = 0; nf < 4; nf++) {
                const int col = wn * 32 + nf * 8 + (lane & 3) * 2;
                const int kt = col >> 5, kk = col & 31;
                char* base = smem + kt * ATILE + kk * 2;
                const float bb0 = b_in[col], bb1 = b_in[col + 1];
#pragma unroll
                for (int hrow = 0; hrow < 2; hrow++) {
                    const int row = row0 + hrow * 8;
                    float va = (accA[mf][nf][hrow * 2 + 0] + accB[mf][nf][hrow * 2 + 0]) * inv + bb0;
                    float vb = (accA[mf][nf][hrow * 2 + 1] + accB[mf][nf][hrow * 2 + 1]) * inv + bb1;
                    va *= 32.f; vb *= 32.f;
                    __half a0, a1, a2, b0, b1, b2;
                    split3(va, a0, a1, a2);
                    split3(vb, b0, b1, b2);
                    char* d = base + row * ROWB;
                    *(__half2*)(d + 0 * CSTRIDE) = __halves2half2(a0, b0);
                    *(__half2*)(d + 1 * CSTRIDE) = __halves2half2(a1, b1);
                    *(__half2*)(d + 2 * CSTRIDE) = __halves2half2(a2, b2);
                }
            }
        }
    }
    cpa_wait_all();
    __syncthreads();

    // ---------------- phase 2: 4 layers x 4 k-tiles ----------------
#pragma unroll
    for (int i = 0; i < 4; i++)
#pragma unroll
        for (int j = 0; j < 4; j++)
#pragma unroll
            for (int k = 0; k < 4; k++) { accA[i][j][k] = 0.f; accB[i][j][k] = 0.f; }

    const float inv = 1.0f / 1024.0f;
    for (int s = 0; s < 16; s++) {
        const int l = s >> 2, kt = s & 3;
        if (s + 1 < 16) stage_B2((s + 1) >> 2, (s + 1) & 3, (s + 1) & 1);
        tile_mma(accA, accB, sb + (uint32_t)(kt * ATILE),
                 sb + (uint32_t)(B2OFF + (s & 1) * ATILE), a_lane, b_lane);
        if (kt == 3) {
            float* dst = g_xs + (size_t)l * M_TOTAL * HID;
#pragma unroll
            for (int mf = 0; mf < 4; mf++) {
                const int row0 = m0 + wm * 64 + mf * 16 + (lane >> 2);
#pragma unroll
                for (int nf = 0; nf < 4; nf++) {
                    const int col = wn * 32 + nf * 8 + (lane & 3) * 2;
                    const float bb0 = Abias[l * HID + col];
                    const float bb1 = Abias[l * HID + col + 1];
                    *(float2*)(dst + (size_t)row0 * HID + col) =
                        make_float2((accA[mf][nf][0] + accB[mf][nf][0]) * inv + bb0,
                                    (accA[mf][nf][1] + accB[mf][nf][1]) * inv + bb1);
                    *(float2*)(dst + (size_t)(row0 + 8) * HID + col) =
                        make_float2((accA[mf][nf][2] + accB[mf][nf][2]) * inv + bb0,
                                    (accA[mf][nf][3] + accB[mf][nf][3]) * inv + bb1);
                }
            }
#pragma unroll
            for (int i = 0; i < 4; i++)
#pragma unroll
                for (int j = 0; j < 4; j++)
#pragma unroll
                    for (int k = 0; k < 4; k++) { accA[i][j][k] = 0.f; accB[i][j][k] = 0.f; }
        }
        cpa_wait_all();
        __syncthreads();
    }
}

// ============================================================
// Sequential LIF scan. block=(b,l), thread=h.
// ============================================================
__global__ void scan_kernel(const float* __restrict__ mem0,
                            const float* __restrict__ thr,
                            const float* __restrict__ decay,
                            const float* __restrict__ rstv,
                            float* __restrict__ dout) {
    const int b = blockIdx.x;
    const int l = blockIdx.y;
    const int h = threadIdx.x;

    const float* xp = g_xs + (size_t)l * M_TOTAL * HID + (size_t)b * T_STEPS * HID + h;
    float mem = mem0[(l * BATCH + b) * HID + h];
    float spk = 0.f, rate = 0.f;
    const float th = thr[h], dc = decay[h], rs = rstv[h];
    const bool last = (l == 3);

    float* mo = dout + MEM_OFF + (size_t)b * (T_STEPS + 1) * HID + h;
    float* so = dout + SPK_OFF + (size_t)b * (T_STEPS + 1) * HID + h;
    if (last) { mo[0] = mem; so[0] = 0.f; }

    for (int t = 0; t < T_STEPS; t += 10) {
        float v[10];
#pragma unroll
        for (int j = 0; j < 10; j++) v[j] = xp[(size_t)(t + j) * HID];
#pragma unroll
        for (int j = 0; j < 10; j++) {
            mem = rs * spk + mem * dc * (1.f - spk) + v[j];
            spk = (mem - th > 0.f) ? 1.f : 0.f;
            rate += spk;
            if (last) {
                mo[(size_t)(t + j + 1) * HID] = mem;
                so[(size_t)(t + j + 1) * HID] = spk;
            }
        }
    }
    g_rates[(l * BATCH + b) * HID + h] = rate * (1.f / 300.f);
}

// ============================================================
// Head: block per batch, 640 threads.
// ============================================================
__global__ __launch_bounds__(640) void head_kernel(const float* __restrict__ fc_w,
                                                   const float* __restrict__ fc_b,
                                                   const float* __restrict__ w_out,
                                                   const float* __restrict__ b_out,
                                                   float* __restrict__ dout) {
    const int b = blockIdx.x;
    const int tid = threadIdx.x;
    __shared__ float rs[512];
    __shared__ float cat[512];

    if (tid < 512) {
        int l = tid >> 7, h = tid & 127;
        rs[tid] = g_rates[(l * BATCH + b) * HID + h];
    }
    __syncthreads();

    if (tid < 512) {
        int l = tid >> 7, h = tid & 127;
        const float* W = fc_w + (size_t)l * HID * HID + h;
        const float* rr = &rs[l * HID];
        float a0 = 0.f, a1 = 0.f, a2 = 0.f, a3 = 0.f;
#pragma unroll
        for (int k = 0; k < HID; k += 4) {
            a0 += rr[k + 0] * W[(size_t)(k + 0) * HID];
            a1 += rr[k + 1] * W[(size_t)(k + 1) * HID];
            a2 += rr[k + 2] * W[(size_t)(k + 2) * HID];
            a3 += rr[k + 3] * W[(size_t)(k + 3) * HID];
        }
        float acc = ((a0 + a1) + (a2 + a3)) + fc_b[l * HID + h];
        cat[tid] = fmaxf(acc, 0.f);
    }
    __syncthreads();

    const int w = tid >> 5, lane = tid & 31;
    if (w < OUTD) {
        float acc = 0.f;
#pragma unroll
        for (int k = lane; k < 512; k += 32) acc += cat[k] * w_out[(size_t)k * OUTD + w];
#pragma unroll
        for (int off = 16; off; off >>= 1) acc += __shfl_down_sync(0xffffffffu, acc, off);
        if (lane == 0) dout[OUT_OFF + b * OUTD + w] = acc + b_out[w];
    }
}

// ============================================================
// A_norm = sum |A_w|
// ============================================================
__global__ __launch_bounds__(1024) void norm_kernel(const float* __restrict__ Aw,
                                                    float* __restrict__ dout) {
    __shared__ float s[1024];
    float acc = 0.f;
    const float4* A4 = (const float4*)Aw;
    const int N4 = LAYERS * HID * HID / 4;
    for (int i = threadIdx.x; i < N4; i += 1024) {
        float4 v = A4[i];
        acc += fabsf(v.x) + fabsf(v.y) + fabsf(v.z) + fabsf(v.w);
    }
    s[threadIdx.x] = acc;
    __syncthreads();
    for (int st = 512; st > 0; st >>= 1) {
        if (threadIdx.x < st) s[threadIdx.x] += s[threadIdx.x + st];
        __syncthreads();
    }
    if (threadIdx.x == 0) dout[NORM_OFF] = s[0];
}

// ============================================================
extern "C" void kernel_launch(void* const* d_in, const int* in_sizes, int n_in,
                              void* d_out, int out_size) {
    const float* x     = (const float*)d_in[0];
    const float* w_in  = (const float*)d_in[1];
    const float* b_in  = (const float*)d_in[2];
    const float* A_w   = (const float*)d_in[3];
    const float* A_b   = (const float*)d_in[4];
    const float* fc_w  = (const float*)d_in[5];
    const float* fc_b  = (const float*)d_in[6];
    const float* w_out = (const float*)d_in[7];
    const float* b_out = (const float*)d_in[8];
    const float* thr   = (const float*)d_in[9];
    const float* decay = (const float*)d_in[10];
    const float* rst   = (const float*)d_in[11];
    const float* mem0  = (const float*)d_in[12];
    float* out = (float*)d_out;

    cudaFuncSetAttribute(gemm_fused, cudaFuncAttributeMaxDynamicSharedMemorySize, FUSED_SMEM);

    presplit<<<(HID * KPAD + 255) / 256, 256>>>(w_in, A_w);

    gemm_fused<<<M_TOTAL / 128, 256, FUSED_SMEM>>>(x, b_in, A_b);

    dim3 g3(BATCH, LAYERS);
    scan_kernel<<<g3, 128>>>(mem0, thr, decay, rst, out);

    head_kernel<<<BATCH, 640>>>(fc_w, fc_b, w_out, b_out, out);
    norm_kernel<<<1, 1024>>>(A_w, out);
}

// round 9
// speedup vs baseline: 1.7019x; 1.0644x over previous
#include <cuda_runtime.h>
#include <cuda_fp16.h>
#include <cstdint>

// ---------------- problem constants ----------------
#define T_STEPS 300
#define BATCH   256
#define HID     128
#define D_IN    700
#define KPAD    704
#define LAYERS  4
#define OUTD    20
#define M_TOTAL (T_STEPS * BATCH)   // 76800

#define OUT_OFF  0
#define MEM_OFF  (BATCH * OUTD)
#define SPK_OFF  (MEM_OFF + BATCH * (T_STEPS + 1) * HID)
#define NORM_OFF (SPK_OFF + BATCH * (T_STEPS + 1) * HID)

// ---------------- scratch (device globals; no allocations) ----------------
__device__ float g_xs[(size_t)LAYERS * M_TOTAL * HID];
__device__ float g_rates[LAYERS * BATCH * HID];
// presplit weights (scaled x32), [comp][n][k]
__device__ __align__(16) __half g_wsplit[3][HID][KPAD];
__device__ __align__(16) __half g_asplit[3][LAYERS][HID][HID];

// ---------------- smem tile geometry ----------------
#define ROWB    80
#define CSTRIDE (128 * ROWB)       // 10240 bytes per comp per 32-k tile
#define ATILE   (3 * CSTRIDE)      // 30720: one 3-comp operand tile
#define BUFSZ   (2 * ATILE)        // phase-1 stage buffer: A(3)+B(3)
#define B2OFF   (4 * ATILE)        // phase-2 B dbl-buffer base (122880)
#define FUSED_SMEM (6 * ATILE)     // 184320

// ---------------- helpers ----------------
__device__ __forceinline__ uint32_t smem_u32(const void* p) {
    uint32_t a;
    asm("{ .reg .u64 t; cvta.to.shared.u64 t, %1; cvt.u32.u64 %0, t; }" : "=r"(a) : "l"(p));
    return a;
}
__device__ __forceinline__ void ldsm4(uint32_t* d, uint32_t addr) {
    asm volatile("ldmatrix.sync.aligned.m8n8.x4.shared.b16 {%0,%1,%2,%3}, [%4];"
                 : "=r"(d[0]), "=r"(d[1]), "=r"(d[2]), "=r"(d[3]) : "r"(addr));
}
__device__ __forceinline__ void mma16816(float* d, const uint32_t* a, const uint32_t* b) {
    asm volatile(
        "mma.sync.aligned.m16n8k16.row.col.f32.f16.f16.f32 "
        "{%0,%1,%2,%3}, {%4,%5,%6,%7}, {%8,%9}, {%0,%1,%2,%3};"
        : "+f"(d[0]), "+f"(d[1]), "+f"(d[2]), "+f"(d[3])
        : "r"(a[0]), "r"(a[1]), "r"(a[2]), "r"(a[3]), "r"(b[0]), "r"(b[1]));
}
__device__ __forceinline__ void cpa16(uint32_t s, const void* g) {
    asm volatile("cp.async.cg.shared.global [%0], [%1], 16;" :: "r"(s), "l"(g));
}
__device__ __forceinline__ void cpa_wait_all() {
    asm volatile("cp.async.wait_all;" ::: "memory");
}
// exact 3-way fp16 split
__device__ __forceinline__ void split3(float v, __half& c0, __half& c1, __half& c2) {
    c0 = __float2half_rn(v);
    float r0 = v - __half2float(c0);
    c1 = __float2half_rn(r0);
    c2 = __float2half_rn(r0 - __half2float(c1));
}

// ============================================================
// presplit: w_in and A_w -> 3 fp16 comps (x32), transposed to [n][k]
// ============================================================
__global__ __launch_bounds__(256) void presplit(const float* __restrict__ w_in,
                                                const float* __restrict__ Aw) {
    int i = blockIdx.x * 256 + threadIdx.x;
    if (i < HID * KPAD) {
        int n = i / KPAD, k = i % KPAD;
        float v = (k < D_IN) ? w_in[(size_t)k * HID + n] * 32.f : 0.f;
        __half a, b, c;
        split3(v, a, b, c);
        g_wsplit[0][n][k] = a; g_wsplit[1][n][k] = b; g_wsplit[2][n][k] = c;
    }
    if (i < LAYERS * HID * HID) {
        int l = i >> 14, rem = i & 16383, n = rem >> 7, k = rem & 127;
        float v = Aw[(size_t)l * HID * HID + (size_t)k * HID + n] * 32.f;
        __half a, b, c;
        split3(v, a, b, c);
        g_asplit[0][l][n][k] = a; g_asplit[1][l][n][k] = b; g_asplit[2][l][n][k] = c;
    }
}

// ============================================================
// MMA core (warp tile 32x32): accA = main pass, accB = corrections.
// Pass order per ks identical to previous rounds -> bit-identical outputs.
// ============================================================
__device__ __forceinline__ void tile_mma(float (&accA)[2][4][4], float (&accB)[2][4][4],
                                         uint32_t Ab, uint32_t Bb,
                                         uint32_t a_lane, uint32_t b_lane) {
#pragma unroll
    for (int ks = 0; ks < 2; ks++) {
        uint32_t bf[3][4][2];
#pragma unroll
        for (int c = 0; c < 3; c++)
#pragma unroll
            for (int np = 0; np < 2; np++) {
                uint32_t r4[4];
                ldsm4(r4, Bb + (uint32_t)(c * CSTRIDE + np * 16 * ROWB + ks * 32) + b_lane);
                bf[c][np * 2 + 0][0] = r4[0]; bf[c][np * 2 + 0][1] = r4[1];
                bf[c][np * 2 + 1][0] = r4[2]; bf[c][np * 2 + 1][1] = r4[3];
            }
        uint32_t af[2][4];
#pragma unroll
        for (int mf = 0; mf < 2; mf++)
            ldsm4(af[mf], Ab + (uint32_t)(0 * CSTRIDE + mf * 16 * ROWB + ks * 32) + a_lane);
#pragma unroll
        for (int mf = 0; mf < 2; mf++)
#pragma unroll
            for (int nf = 0; nf < 4; nf++) mma16816(accA[mf][nf], af[mf], bf[0][nf]);
#pragma unroll
        for (int cb = 1; cb < 3; cb++)
#pragma unroll
            for (int mf = 0; mf < 2; mf++)
#pragma unroll
                for (int nf = 0; nf < 4; nf++) mma16816(accB[mf][nf], af[mf], bf[cb][nf]);
#pragma unroll
        for (int mf = 0; mf < 2; mf++)
            ldsm4(af[mf], Ab + (uint32_t)(1 * CSTRIDE + mf * 16 * ROWB + ks * 32) + a_lane);
#pragma unroll
        for (int cb = 0; cb < 2; cb++)
#pragma unroll
            for (int mf = 0; mf < 2; mf++)
#pragma unroll
                for (int nf = 0; nf < 4; nf++) mma16816(accB[mf][nf], af[mf], bf[cb][nf]);
#pragma unroll
        for (int mf = 0; mf < 2; mf++)
            ldsm4(af[mf], Ab + (uint32_t)(2 * CSTRIDE + mf * 16 * ROWB + ks * 32) + a_lane);
#pragma unroll
        for (int mf = 0; mf < 2; mf++)
#pragma unroll
            for (int nf = 0; nf < 4; nf++) mma16816(accB[mf][nf], af[mf], bf[0][nf]);
    }
}

// ============================================================
// FUSED GEMM, 512 threads (16 warps, 4x4 warp grid, warp tile 32x32):
//   phase 1: inp = x @ w_in + b_in (22 k-tiles)
//   epilogue: split3(inp*32) direct to phase-2 smem A layout
//   phase 2: xs[l] = inp @ A_w[l] + A_b[l], 4 layers x 4 k-tiles
// ============================================================
__global__ __launch_bounds__(512, 1) void gemm_fused(const float* __restrict__ x,
                                                     const float* __restrict__ b_in,
                                                     const float* __restrict__ Abias) {
    extern __shared__ char smem[];
    const uint32_t sb = smem_u32(smem);
    const int tid = threadIdx.x, lane = tid & 31, wid = tid >> 5;
    const int wm = wid & 3, wn = wid >> 2;
    const int m0 = blockIdx.x * 128;
    const int q = lane >> 3, r = lane & 7;
    const uint32_t a_lane = (uint32_t)((wm * 32 + (q & 1) * 8 + r) * ROWB + ((q >> 1) * 8) * 2);
    const uint32_t b_lane = (uint32_t)((wn * 32 + (q >> 1) * 8 + r) * ROWB + ((q & 1) * 8) * 2);

    float accA[2][4][4], accB[2][4][4];
#pragma unroll
    for (int i = 0; i < 2; i++)
#pragma unroll
        for (int j = 0; j < 4; j++)
#pragma unroll
            for (int k = 0; k < 4; k++) { accA[i][j][k] = 0.f; accB[i][j][k] = 0.f; }

    // ---------------- phase 1 ----------------
    float4 u0, u1;
    const int srow = tid >> 2, skg = (tid & 3) * 8;   // staging coords (512 thr, 1 group)

    auto load_x = [&](int t) {
        const int k = t * 32 + skg;
        const float* p = x + (size_t)(m0 + srow) * D_IN + k;
        u0 = *(const float4*)p;
        u1 = (k + 4 < D_IN) ? *(const float4*)(p + 4) : make_float4(0.f, 0.f, 0.f, 0.f);
    };
    auto store_A = [&](int buf) {
        char* Abp = smem + buf * BUFSZ;
        float v[8] = {u0.x, u0.y, u0.z, u0.w, u1.x, u1.y, u1.z, u1.w};
        __align__(16) __half h0[8], h1[8], h2[8];
#pragma unroll
        for (int j = 0; j < 8; j++) split3(v[j] * 32.f, h0[j], h1[j], h2[j]);
        char* d = Abp + srow * ROWB + skg * 2;
        *(uint4*)(d + 0 * CSTRIDE) = *(uint4*)h0;
        *(uint4*)(d + 1 * CSTRIDE) = *(uint4*)h1;
        *(uint4*)(d + 2 * CSTRIDE) = *(uint4*)h2;
    };
    auto issue_B = [&](int t, int buf) {
        const int k0 = t * 32;
        const uint32_t Bb = sb + (uint32_t)(buf * BUFSZ + ATILE);
#pragma unroll
        for (int c = 0; c < 3; c++)
            cpa16(Bb + (uint32_t)(c * CSTRIDE + srow * ROWB + (tid & 3) * 16),
                  &g_wsplit[c][srow][k0 + skg]);
    };

    load_x(0);
    store_A(0);
    issue_B(0, 0);
    cpa_wait_all();
    __syncthreads();

    for (int t = 0; t < 22; t++) {
        const bool more = (t + 1) < 22;
        if (more) {
            load_x(t + 1);
            issue_B(t + 1, (t + 1) & 1);
        }
        const uint32_t base = sb + (uint32_t)((t & 1) * BUFSZ);
        tile_mma(accA, accB, base, base + ATILE, a_lane, b_lane);
        if (more) store_A((t + 1) & 1);
        cpa_wait_all();
        __syncthreads();
    }

    // ---------------- phase-2 B staging ----------------
    auto stage_B2 = [&](int l, int kt, int buf) {
        const int k0 = kt * 32;
        const uint32_t Bb = sb + (uint32_t)(B2OFF + buf * ATILE);
#pragma unroll
        for (int c = 0; c < 3; c++)
            cpa16(Bb + (uint32_t)(c * CSTRIDE + srow * ROWB + (tid & 3) * 16),
                  &g_asplit[c][l][srow][k0 + skg]);
    };

    stage_B2(0, 0, 0);

    // ---------------- epilogue 1: split inp into phase-2 A layout ----------------
    {
        const float inv = 1.0f / 1024.0f;
#pragma unroll
        for (int mf = 0; mf < 2; mf++) {
            const int row0 = wm * 32 + mf * 16 + (lane >> 2);
#pragma unroll
            for (int nf = 0; nf < 4; nf++) {
                const int col = wn * 32 + nf * 8 + (lane & 3) * 2;
                const int kt = col >> 5, kk = col & 31;
                char* base = smem + kt * ATILE + kk * 2;
                const float bb0 = b_in[col], bb1 = b_in[col + 1];
#pragma unroll
                for (int hrow = 0; hrow < 2; hrow++) {
                    const int row = row0 + hrow * 8;
                    float va = (accA[mf][nf][hrow * 2 + 0] + accB[mf][nf][hrow * 2 + 0]) * inv + bb0;
                    float vb = (accA[mf][nf][hrow * 2 + 1] + accB[mf][nf][hrow * 2 + 1]) * inv + bb1;
                    va *= 32.f; vb *= 32.f;
                    __half a0, a1, a2, b0, b1, b2;
                    split3(va, a0, a1, a2);
                    split3(vb, b0, b1, b2);
                    char* d = base + row * ROWB;
                    *(__half2*)(d + 0 * CSTRIDE) = __halves2half2(a0, b0);
                    *(__half2*)(d + 1 * CSTRIDE) = __halves2half2(a1, b1);
                    *(__half2*)(d + 2 * CSTRIDE) = __halves2half2(a2, b2);
                }
            }
        }
    }
    cpa_wait_all();
    __syncthreads();

    // ---------------- phase 2: 4 layers x 4 k-tiles ----------------
#pragma unroll
    for (int i = 0; i < 2; i++)
#pragma unroll
        for (int j = 0; j < 4; j++)
#pragma unroll
            for (int k = 0; k < 4; k++) { accA[i][j][k] = 0.f; accB[i][j][k] = 0.f; }

    const float inv = 1.0f / 1024.0f;
    for (int s = 0; s < 16; s++) {
        const int l = s >> 2, kt = s & 3;
        if (s + 1 < 16) stage_B2((s + 1) >> 2, (s + 1) & 3, (s + 1) & 1);
        tile_mma(accA, accB, sb + (uint32_t)(kt * ATILE),
                 sb + (uint32_t)(B2OFF + (s & 1) * ATILE), a_lane, b_lane);
        if (kt == 3) {
            float* dst = g_xs + (size_t)l * M_TOTAL * HID;
#pragma unroll
            for (int mf = 0; mf < 2; mf++) {
                const int row0 = m0 + wm * 32 + mf * 16 + (lane >> 2);
#pragma unroll
                for (int nf = 0; nf < 4; nf++) {
                    const int col = wn * 32 + nf * 8 + (lane & 3) * 2;
                    const float bb0 = Abias[l * HID + col];
                    const float bb1 = Abias[l * HID + col + 1];
                    *(float2*)(dst + (size_t)row0 * HID + col) =
                        make_float2((accA[mf][nf][0] + accB[mf][nf][0]) * inv + bb0,
                                    (accA[mf][nf][1] + accB[mf][nf][1]) * inv + bb1);
                    *(float2*)(dst + (size_t)(row0 + 8) * HID + col) =
                        make_float2((accA[mf][nf][2] + accB[mf][nf][2]) * inv + bb0,
                                    (accA[mf][nf][3] + accB[mf][nf][3]) * inv + bb1);
                }
            }
#pragma unroll
            for (int i = 0; i < 2; i++)
#pragma unroll
                for (int j = 0; j < 4; j++)
#pragma unroll
                    for (int k = 0; k < 4; k++) { accA[i][j][k] = 0.f; accB[i][j][k] = 0.f; }
        }
        cpa_wait_all();
        __syncthreads();
    }
}

// ============================================================
// Sequential LIF scan. block=(b,l), thread=h.
// ============================================================
__global__ void scan_kernel(const float* __restrict__ mem0,
                            const float* __restrict__ thr,
                            const float* __restrict__ decay,
                            const float* __restrict__ rstv,
                            float* __restrict__ dout) {
    const int b = blockIdx.x;
    const int l = blockIdx.y;
    const int h = threadIdx.x;

    const float* xp = g_xs + (size_t)l * M_TOTAL * HID + (size_t)b * T_STEPS * HID + h;
    float mem = mem0[(l * BATCH + b) * HID + h];
    float spk = 0.f, rate = 0.f;
    const float th = thr[h], dc = decay[h], rs = rstv[h];
    const bool last = (l == 3);

    float* mo = dout + MEM_OFF + (size_t)b * (T_STEPS + 1) * HID + h;
    float* so = dout + SPK_OFF + (size_t)b * (T_STEPS + 1) * HID + h;
    if (last) { mo[0] = mem; so[0] = 0.f; }

    for (int t = 0; t < T_STEPS; t += 10) {
        float v[10];
#pragma unroll
        for (int j = 0; j < 10; j++) v[j] = xp[(size_t)(t + j) * HID];
#pragma unroll
        for (int j = 0; j < 10; j++) {
            mem = rs * spk + mem * dc * (1.f - spk) + v[j];
            spk = (mem - th > 0.f) ? 1.f : 0.f;
            rate += spk;
            if (last) {
                mo[(size_t)(t + j + 1) * HID] = mem;
                so[(size_t)(t + j + 1) * HID] = spk;
            }
        }
    }
    g_rates[(l * BATCH + b) * HID + h] = rate * (1.f / 300.f);
}

// ============================================================
// Head: block per batch, 640 threads.
// ============================================================
__global__ __launch_bounds__(640) void head_kernel(const float* __restrict__ fc_w,
                                                   const float* __restrict__ fc_b,
                                                   const float* __restrict__ w_out,
                                                   const float* __restrict__ b_out,
                                                   float* __restrict__ dout) {
    const int b = blockIdx.x;
    const int tid = threadIdx.x;
    __shared__ float rs[512];
    __shared__ float cat[512];

    if (tid < 512) {
        int l = tid >> 7, h = tid & 127;
        rs[tid] = g_rates[(l * BATCH + b) * HID + h];
    }
    __syncthreads();

    if (tid < 512) {
        int l = tid >> 7, h = tid & 127;
        const float* W = fc_w + (size_t)l * HID * HID + h;
        const float* rr = &rs[l * HID];
        float a0 = 0.f, a1 = 0.f, a2 = 0.f, a3 = 0.f;
#pragma unroll
        for (int k = 0; k < HID; k += 4) {
            a0 += rr[k + 0] * W[(size_t)(k + 0) * HID];
            a1 += rr[k + 1] * W[(size_t)(k + 1) * HID];
            a2 += rr[k + 2] * W[(size_t)(k + 2) * HID];
            a3 += rr[k + 3] * W[(size_t)(k + 3) * HID];
        }
        float acc = ((a0 + a1) + (a2 + a3)) + fc_b[l * HID + h];
        cat[tid] = fmaxf(acc, 0.f);
    }
    __syncthreads();

    const int w = tid >> 5, lane = tid & 31;
    if (w < OUTD) {
        float acc = 0.f;
#pragma unroll
        for (int k = lane; k < 512; k += 32) acc += cat[k] * w_out[(size_t)k * OUTD + w];
#pragma unroll
        for (int off = 16; off; off >>= 1) acc += __shfl_down_sync(0xffffffffu, acc, off);
        if (lane == 0) dout[OUT_OFF + b * OUTD + w] = acc + b_out[w];
    }
}

// ============================================================
// A_norm = sum |A_w|
// ============================================================
__global__ __launch_bounds__(1024) void norm_kernel(const float* __restrict__ Aw,
                                                    float* __restrict__ dout) {
    __shared__ float s[1024];
    float acc = 0.f;
    const float4* A4 = (const float4*)Aw;
    const int N4 = LAYERS * HID * HID / 4;
    for (int i = threadIdx.x; i < N4; i += 1024) {
        float4 v = A4[i];
        acc += fabsf(v.x) + fabsf(v.y) + fabsf(v.z) + fabsf(v.w);
    }
    s[threadIdx.x] = acc;
    __syncthreads();
    for (int st = 512; st > 0; st >>= 1) {
        if (threadIdx.x < st) s[threadIdx.x] += s[threadIdx.x + st];
        __syncthreads();
    }
    if (threadIdx.x == 0) dout[NORM_OFF] = s[0];
}

// ============================================================
extern "C" void kernel_launch(void* const* d_in, const int* in_sizes, int n_in,
                              void* d_out, int out_size) {
    const float* x     = (const float*)d_in[0];
    const float* w_in  = (const float*)d_in[1];
    const float* b_in  = (const float*)d_in[2];
    const float* A_w   = (const float*)d_in[3];
    const float* A_b   = (const float*)d_in[4];
    const float* fc_w  = (const float*)d_in[5];
    const float* fc_b  = (const float*)d_in[6];
    const float* w_out = (const float*)d_in[7];
    const float* b_out = (const float*)d_in[8];
    const float* thr   = (const float*)d_in[9];
    const float* decay = (const float*)d_in[10];
    const float* rst   = (const float*)d_in[11];
    const float* mem0  = (const float*)d_in[12];
    float* out = (float*)d_out;

    cudaFuncSetAttribute(gemm_fused, cudaFuncAttributeMaxDynamicSharedMemorySize, FUSED_SMEM);

    presplit<<<(HID * KPAD + 255) / 256, 256>>>(w_in, A_w);

    gemm_fused<<<M_TOTAL / 128, 512, FUSED_SMEM>>>(x, b_in, A_b);

    dim3 g3(BATCH, LAYERS);
    scan_kernel<<<g3, 128>>>(mem0, thr, decay, rst, out);

    head_kernel<<<BATCH, 640>>>(fc_w, fc_b, w_out, b_out, out);
    norm_kernel<<<1, 1024>>>(A_w, out);
}

// round 10
// speedup vs baseline: 1.8354x; 1.0784x over previous
#include <cuda_runtime.h>
#include <cuda_fp16.h>
#include <cstdint>

// ---------------- problem constants ----------------
#define T_STEPS 300
#define BATCH   256
#define HID     128
#define D_IN    700
#define KPAD    704
#define LAYERS  4
#define OUTD    20
#define M_TOTAL (T_STEPS * BATCH)   // 76800

#define OUT_OFF  0
#define MEM_OFF  (BATCH * OUTD)
#define SPK_OFF  (MEM_OFF + BATCH * (T_STEPS + 1) * HID)
#define NORM_OFF (SPK_OFF + BATCH * (T_STEPS + 1) * HID)

// ---------------- scratch (device globals; no allocations) ----------------
__device__ float g_xs[(size_t)LAYERS * M_TOTAL * HID];
__device__ float g_rates[LAYERS * BATCH * HID];
// presplit weights (scaled x32), [comp][n][k]
__device__ __align__(16) __half g_wsplit[3][HID][KPAD];
__device__ __align__(16) __half g_asplit[3][LAYERS][HID][HID];

// ---------------- smem tile geometry ----------------
#define ROWB    80
#define CSTRIDE (128 * ROWB)       // 10240 bytes per comp per 32-k tile
#define ATILE   (3 * CSTRIDE)      // 30720: one 3-comp operand tile
#define BUFSZ   (2 * ATILE)        // phase-1 stage buffer: A(3)+B(3)
#define B2OFF   (4 * ATILE)        // phase-2 B dbl-buffer base (122880)
#define FUSED_SMEM (6 * ATILE)     // 184320

// ---------------- helpers ----------------
__device__ __forceinline__ uint32_t smem_u32(const void* p) {
    uint32_t a;
    asm("{ .reg .u64 t; cvta.to.shared.u64 t, %1; cvt.u32.u64 %0, t; }" : "=r"(a) : "l"(p));
    return a;
}
__device__ __forceinline__ void ldsm4(uint32_t* d, uint32_t addr) {
    asm volatile("ldmatrix.sync.aligned.m8n8.x4.shared.b16 {%0,%1,%2,%3}, [%4];"
                 : "=r"(d[0]), "=r"(d[1]), "=r"(d[2]), "=r"(d[3]) : "r"(addr));
}
__device__ __forceinline__ void mma16816(float* d, const uint32_t* a, const uint32_t* b) {
    asm volatile(
        "mma.sync.aligned.m16n8k16.row.col.f32.f16.f16.f32 "
        "{%0,%1,%2,%3}, {%4,%5,%6,%7}, {%8,%9}, {%0,%1,%2,%3};"
        : "+f"(d[0]), "+f"(d[1]), "+f"(d[2]), "+f"(d[3])
        : "r"(a[0]), "r"(a[1]), "r"(a[2]), "r"(a[3]), "r"(b[0]), "r"(b[1]));
}
__device__ __forceinline__ void cpa16(uint32_t s, const void* g) {
    asm volatile("cp.async.cg.shared.global [%0], [%1], 16;" :: "r"(s), "l"(g));
}
__device__ __forceinline__ void cpa_wait_all() {
    asm volatile("cp.async.wait_all;" ::: "memory");
}
// exact 3-way fp16 split
__device__ __forceinline__ void split3(float v, __half& c0, __half& c1, __half& c2) {
    c0 = __float2half_rn(v);
    float r0 = v - __half2float(c0);
    c1 = __float2half_rn(r0);
    c2 = __float2half_rn(r0 - __half2float(c1));
}

// ============================================================
// presplit: w_in and A_w -> 3 fp16 comps (x32), transposed to [n][k]
// ============================================================
__global__ __launch_bounds__(256) void presplit(const float* __restrict__ w_in,
                                                const float* __restrict__ Aw) {
    int i = blockIdx.x * 256 + threadIdx.x;
    if (i < HID * KPAD) {
        int n = i / KPAD, k = i % KPAD;
        float v = (k < D_IN) ? w_in[(size_t)k * HID + n] * 32.f : 0.f;
        __half a, b, c;
        split3(v, a, b, c);
        g_wsplit[0][n][k] = a; g_wsplit[1][n][k] = b; g_wsplit[2][n][k] = c;
    }
    if (i < LAYERS * HID * HID) {
        int l = i >> 14, rem = i & 16383, n = rem >> 7, k = rem & 127;
        float v = Aw[(size_t)l * HID * HID + (size_t)k * HID + n] * 32.f;
        __half a, b, c;
        split3(v, a, b, c);
        g_asplit[0][l][n][k] = a; g_asplit[1][l][n][k] = b; g_asplit[2][l][n][k] = c;
    }
}

// ============================================================
// MMA core (warp tile 32x32), 5 passes:
//   accA += a0*b0                      (full magnitude)
//   accB += a0*b1 + a0*b2 + a1*b0 + a2*b0   (first-order corrections)
// a1*b1 dropped: second-order (~2^-26 rel), 15x below fp32 noise floor.
// ============================================================
__device__ __forceinline__ void tile_mma(float (&accA)[2][4][4], float (&accB)[2][4][4],
                                         uint32_t Ab, uint32_t Bb,
                                         uint32_t a_lane, uint32_t b_lane) {
#pragma unroll
    for (int ks = 0; ks < 2; ks++) {
        uint32_t bf[3][4][2];
#pragma unroll
        for (int c = 0; c < 3; c++)
#pragma unroll
            for (int np = 0; np < 2; np++) {
                uint32_t r4[4];
                ldsm4(r4, Bb + (uint32_t)(c * CSTRIDE + np * 16 * ROWB + ks * 32) + b_lane);
                bf[c][np * 2 + 0][0] = r4[0]; bf[c][np * 2 + 0][1] = r4[1];
                bf[c][np * 2 + 1][0] = r4[2]; bf[c][np * 2 + 1][1] = r4[3];
            }
        uint32_t af[2][4];
        // a0: b0 -> accA ; b1, b2 -> accB
#pragma unroll
        for (int mf = 0; mf < 2; mf++)
            ldsm4(af[mf], Ab + (uint32_t)(0 * CSTRIDE + mf * 16 * ROWB + ks * 32) + a_lane);
#pragma unroll
        for (int mf = 0; mf < 2; mf++)
#pragma unroll
            for (int nf = 0; nf < 4; nf++) mma16816(accA[mf][nf], af[mf], bf[0][nf]);
#pragma unroll
        for (int cb = 1; cb < 3; cb++)
#pragma unroll
            for (int mf = 0; mf < 2; mf++)
#pragma unroll
                for (int nf = 0; nf < 4; nf++) mma16816(accB[mf][nf], af[mf], bf[cb][nf]);
        // a1: b0 only -> accB  (a1*b1 dropped)
#pragma unroll
        for (int mf = 0; mf < 2; mf++)
            ldsm4(af[mf], Ab + (uint32_t)(1 * CSTRIDE + mf * 16 * ROWB + ks * 32) + a_lane);
#pragma unroll
        for (int mf = 0; mf < 2; mf++)
#pragma unroll
            for (int nf = 0; nf < 4; nf++) mma16816(accB[mf][nf], af[mf], bf[0][nf]);
        // a2: b0 -> accB
#pragma unroll
        for (int mf = 0; mf < 2; mf++)
            ldsm4(af[mf], Ab + (uint32_t)(2 * CSTRIDE + mf * 16 * ROWB + ks * 32) + a_lane);
#pragma unroll
        for (int mf = 0; mf < 2; mf++)
#pragma unroll
            for (int nf = 0; nf < 4; nf++) mma16816(accB[mf][nf], af[mf], bf[0][nf]);
    }
}

// ============================================================
// FUSED GEMM, 512 threads (16 warps, 4x4 warp grid, warp tile 32x32):
//   phase 1: inp = x @ w_in + b_in (22 k-tiles)
//   epilogue: split3(inp*32) direct to phase-2 smem A layout
//   phase 2: xs[l] = inp @ A_w[l] + A_b[l], 4 layers x 4 k-tiles
// ============================================================
__global__ __launch_bounds__(512, 1) void gemm_fused(const float* __restrict__ x,
                                                     const float* __restrict__ b_in,
                                                     const float* __restrict__ Abias) {
    extern __shared__ char smem[];
    const uint32_t sb = smem_u32(smem);
    const int tid = threadIdx.x, lane = tid & 31, wid = tid >> 5;
    const int wm = wid & 3, wn = wid >> 2;
    const int m0 = blockIdx.x * 128;
    const int q = lane >> 3, r = lane & 7;
    const uint32_t a_lane = (uint32_t)((wm * 32 + (q & 1) * 8 + r) * ROWB + ((q >> 1) * 8) * 2);
    const uint32_t b_lane = (uint32_t)((wn * 32 + (q >> 1) * 8 + r) * ROWB + ((q & 1) * 8) * 2);

    float accA[2][4][4], accB[2][4][4];
#pragma unroll
    for (int i = 0; i < 2; i++)
#pragma unroll
        for (int j = 0; j < 4; j++)
#pragma unroll
            for (int k = 0; k < 4; k++) { accA[i][j][k] = 0.f; accB[i][j][k] = 0.f; }

    // ---------------- phase 1 ----------------
    float4 u0, u1;
    const int srow = tid >> 2, skg = (tid & 3) * 8;

    auto load_x = [&](int t) {
        const int k = t * 32 + skg;
        const float* p = x + (size_t)(m0 + srow) * D_IN + k;
        u0 = *(const float4*)p;
        u1 = (k + 4 < D_IN) ? *(const float4*)(p + 4) : make_float4(0.f, 0.f, 0.f, 0.f);
    };
    auto store_A = [&](int buf) {
        char* Abp = smem + buf * BUFSZ;
        float v[8] = {u0.x, u0.y, u0.z, u0.w, u1.x, u1.y, u1.z, u1.w};
        __align__(16) __half h0[8], h1[8], h2[8];
#pragma unroll
        for (int j = 0; j < 8; j++) split3(v[j] * 32.f, h0[j], h1[j], h2[j]);
        char* d = Abp + srow * ROWB + skg * 2;
        *(uint4*)(d + 0 * CSTRIDE) = *(uint4*)h0;
        *(uint4*)(d + 1 * CSTRIDE) = *(uint4*)h1;
        *(uint4*)(d + 2 * CSTRIDE) = *(uint4*)h2;
    };
    auto issue_B = [&](int t, int buf) {
        const int k0 = t * 32;
        const uint32_t Bb = sb + (uint32_t)(buf * BUFSZ + ATILE);
#pragma unroll
        for (int c = 0; c < 3; c++)
            cpa16(Bb + (uint32_t)(c * CSTRIDE + srow * ROWB + (tid & 3) * 16),
                  &g_wsplit[c][srow][k0 + skg]);
    };

    load_x(0);
    store_A(0);
    issue_B(0, 0);
    cpa_wait_all();
    __syncthreads();

    for (int t = 0; t < 22; t++) {
        const bool more = (t + 1) < 22;
        if (more) {
            load_x(t + 1);
            issue_B(t + 1, (t + 1) & 1);
        }
        const uint32_t base = sb + (uint32_t)((t & 1) * BUFSZ);
        tile_mma(accA, accB, base, base + ATILE, a_lane, b_lane);
        if (more) store_A((t + 1) & 1);
        cpa_wait_all();
        __syncthreads();
    }

    // ---------------- phase-2 B staging ----------------
    auto stage_B2 = [&](int l, int kt, int buf) {
        const int k0 = kt * 32;
        const uint32_t Bb = sb + (uint32_t)(B2OFF + buf * ATILE);
#pragma unroll
        for (int c = 0; c < 3; c++)
            cpa16(Bb + (uint32_t)(c * CSTRIDE + srow * ROWB + (tid & 3) * 16),
                  &g_asplit[c][l][srow][k0 + skg]);
    };

    stage_B2(0, 0, 0);

    // ---------------- epilogue 1: split inp into phase-2 A layout ----------------
    {
        const float inv = 1.0f / 1024.0f;
#pragma unroll
        for (int mf = 0; mf < 2; mf++) {
            const int row0 = wm * 32 + mf * 16 + (lane >> 2);
#pragma unroll
            for (int nf = 0; nf < 4; nf++) {
                const int col = wn * 32 + nf * 8 + (lane & 3) * 2;
                const int kt = col >> 5, kk = col & 31;
                char* base = smem + kt * ATILE + kk * 2;
                const float bb0 = b_in[col], bb1 = b_in[col + 1];
#pragma unroll
                for (int hrow = 0; hrow < 2; hrow++) {
                    const int row = row0 + hrow * 8;
                    float va = (accA[mf][nf][hrow * 2 + 0] + accB[mf][nf][hrow * 2 + 0]) * inv + bb0;
                    float vb = (accA[mf][nf][hrow * 2 + 1] + accB[mf][nf][hrow * 2 + 1]) * inv + bb1;
                    va *= 32.f; vb *= 32.f;
                    __half a0, a1, a2, b0, b1, b2;
                    split3(va, a0, a1, a2);
                    split3(vb, b0, b1, b2);
                    char* d = base + row * ROWB;
                    *(__half2*)(d + 0 * CSTRIDE) = __halves2half2(a0, b0);
                    *(__half2*)(d + 1 * CSTRIDE) = __halves2half2(a1, b1);
                    *(__half2*)(d + 2 * CSTRIDE) = __halves2half2(a2, b2);
                }
            }
        }
    }
    cpa_wait_all();
    __syncthreads();

    // ---------------- phase 2: 4 layers x 4 k-tiles ----------------
#pragma unroll
    for (int i = 0; i < 2; i++)
#pragma unroll
        for (int j = 0; j < 4; j++)
#pragma unroll
            for (int k = 0; k < 4; k++) { accA[i][j][k] = 0.f; accB[i][j][k] = 0.f; }

    const float inv = 1.0f / 1024.0f;
    for (int s = 0; s < 16; s++) {
        const int l = s >> 2, kt = s & 3;
        if (s + 1 < 16) stage_B2((s + 1) >> 2, (s + 1) & 3, (s + 1) & 1);
        tile_mma(accA, accB, sb + (uint32_t)(kt * ATILE),
                 sb + (uint32_t)(B2OFF + (s & 1) * ATILE), a_lane, b_lane);
        if (kt == 3) {
            float* dst = g_xs + (size_t)l * M_TOTAL * HID;
#pragma unroll
            for (int mf = 0; mf < 2; mf++) {
                const int row0 = m0 + wm * 32 + mf * 16 + (lane >> 2);
#pragma unroll
                for (int nf = 0; nf < 4; nf++) {
                    const int col = wn * 32 + nf * 8 + (lane & 3) * 2;
                    const float bb0 = Abias[l * HID + col];
                    const float bb1 = Abias[l * HID + col + 1];
                    *(float2*)(dst + (size_t)row0 * HID + col) =
                        make_float2((accA[mf][nf][0] + accB[mf][nf][0]) * inv + bb0,
                                    (accA[mf][nf][1] + accB[mf][nf][1]) * inv + bb1);
                    *(float2*)(dst + (size_t)(row0 + 8) * HID + col) =
                        make_float2((accA[mf][nf][2] + accB[mf][nf][2]) * inv + bb0,
                                    (accA[mf][nf][3] + accB[mf][nf][3]) * inv + bb1);
                }
            }
#pragma unroll
            for (int i = 0; i < 2; i++)
#pragma unroll
                for (int j = 0; j < 4; j++)
#pragma unroll
                    for (int k = 0; k < 4; k++) { accA[i][j][k] = 0.f; accB[i][j][k] = 0.f; }
        }
        cpa_wait_all();
        __syncthreads();
    }
}

// ============================================================
// Sequential LIF scan. block=(b,l), thread=h.
// ============================================================
__global__ void scan_kernel(const float* __restrict__ mem0,
                            const float* __restrict__ thr,
                            const float* __restrict__ decay,
                            const float* __restrict__ rstv,
                            float* __restrict__ dout) {
    const int b = blockIdx.x;
    const int l = blockIdx.y;
    const int h = threadIdx.x;

    const float* xp = g_xs + (size_t)l * M_TOTAL * HID + (size_t)b * T_STEPS * HID + h;
    float mem = mem0[(l * BATCH + b) * HID + h];
    float spk = 0.f, rate = 0.f;
    const float th = thr[h], dc = decay[h], rs = rstv[h];
    const bool last = (l == 3);

    float* mo = dout + MEM_OFF + (size_t)b * (T_STEPS + 1) * HID + h;
    float* so = dout + SPK_OFF + (size_t)b * (T_STEPS + 1) * HID + h;
    if (last) { mo[0] = mem; so[0] = 0.f; }

    for (int t = 0; t < T_STEPS; t += 10) {
        float v[10];
#pragma unroll
        for (int j = 0; j < 10; j++) v[j] = xp[(size_t)(t + j) * HID];
#pragma unroll
        for (int j = 0; j < 10; j++) {
            mem = rs * spk + mem * dc * (1.f - spk) + v[j];
            spk = (mem - th > 0.f) ? 1.f : 0.f;
            rate += spk;
            if (last) {
                mo[(size_t)(t + j + 1) * HID] = mem;
                so[(size_t)(t + j + 1) * HID] = spk;
            }
        }
    }
    g_rates[(l * BATCH + b) * HID + h] = rate * (1.f / 300.f);
}

// ============================================================
// Head: block per batch, 640 threads.
// ============================================================
__global__ __launch_bounds__(640) void head_kernel(const float* __restrict__ fc_w,
                                                   const float* __restrict__ fc_b,
                                                   const float* __restrict__ w_out,
                                                   const float* __restrict__ b_out,
                                                   float* __restrict__ dout) {
    const int b = blockIdx.x;
    const int tid = threadIdx.x;
    __shared__ float rs[512];
    __shared__ float cat[512];

    if (tid < 512) {
        int l = tid >> 7, h = tid & 127;
        rs[tid] = g_rates[(l * BATCH + b) * HID + h];
    }
    __syncthreads();

    if (tid < 512) {
        int l = tid >> 7, h = tid & 127;
        const float* W = fc_w + (size_t)l * HID * HID + h;
        const float* rr = &rs[l * HID];
        float a0 = 0.f, a1 = 0.f, a2 = 0.f, a3 = 0.f;
#pragma unroll
        for (int k = 0; k < HID; k += 4) {
            a0 += rr[k + 0] * W[(size_t)(k + 0) * HID];
            a1 += rr[k + 1] * W[(size_t)(k + 1) * HID];
            a2 += rr[k + 2] * W[(size_t)(k + 2) * HID];
            a3 += rr[k + 3] * W[(size_t)(k + 3) * HID];
        }
        float acc = ((a0 + a1) + (a2 + a3)) + fc_b[l * HID + h];
        cat[tid] = fmaxf(acc, 0.f);
    }
    __syncthreads();

    const int w = tid >> 5, lane = tid & 31;
    if (w < OUTD) {
        float acc = 0.f;
#pragma unroll
        for (int k = lane; k < 512; k += 32) acc += cat[k] * w_out[(size_t)k * OUTD + w];
#pragma unroll
        for (int off = 16; off; off >>= 1) acc += __shfl_down_sync(0xffffffffu, acc, off);
        if (lane == 0) dout[OUT_OFF + b * OUTD + w] = acc + b_out[w];
    }
}

// ============================================================
// A_norm = sum |A_w|
// ============================================================
__global__ __launch_bounds__(1024) void norm_kernel(const float* __restrict__ Aw,
                                                    float* __restrict__ dout) {
    __shared__ float s[1024];
    float acc = 0.f;
    const float4* A4 = (const float4*)Aw;
    const int N4 = LAYERS * HID * HID / 4;
    for (int i = threadIdx.x; i < N4; i += 1024) {
        float4 v = A4[i];
        acc += fabsf(v.x) + fabsf(v.y) + fabsf(v.z) + fabsf(v.w);
    }
    s[threadIdx.x] = acc;
    __syncthreads();
    for (int st = 512; st > 0; st >>= 1) {
        if (threadIdx.x < st) s[threadIdx.x] += s[threadIdx.x + st];
        __syncthreads();
    }
    if (threadIdx.x == 0) dout[NORM_OFF] = s[0];
}

// ============================================================
extern "C" void kernel_launch(void* const* d_in, const int* in_sizes, int n_in,
                              void* d_out, int out_size) {
    const float* x     = (const float*)d_in[0];
    const float* w_in  = (const float*)d_in[1];
    const float* b_in  = (const float*)d_in[2];
    const float* A_w   = (const float*)d_in[3];
    const float* A_b   = (const float*)d_in[4];
    const float* fc_w  = (const float*)d_in[5];
    const float* fc_b  = (const float*)d_in[6];
    const float* w_out = (const float*)d_in[7];
    const float* b_out = (const float*)d_in[8];
    const float* thr   = (const float*)d_in[9];
    const float* decay = (const float*)d_in[10];
    const float* rst   = (const float*)d_in[11];
    const float* mem0  = (const float*)d_in[12];
    float* out = (float*)d_out;

    cudaFuncSetAttribute(gemm_fused, cudaFuncAttributeMaxDynamicSharedMemorySize, FUSED_SMEM);

    presplit<<<(HID * KPAD + 255) / 256, 256>>>(w_in, A_w);

    gemm_fused<<<M_TOTAL / 128, 512, FUSED_SMEM>>>(x, b_in, A_b);

    dim3 g3(BATCH, LAYERS);
    scan_kernel<<<g3, 128>>>(mem0, thr, decay, rst, out);

    head_kernel<<<BATCH, 640>>>(fc_w, fc_b, w_out, b_out, out);
    norm_kernel<<<1, 1024>>>(A_w, out);
}